// round 1
// baseline (speedup 1.0000x reference)
#include <cuda_runtime.h>
#include <math.h>

#define BB 32
#define TT 64
#define VV 8000
#define EE 256
#define HH 512
#define GG 2048            // 4*H
#define WW 3
#define NEGF (-1e30f)
#define NDROW 4096         // decoder rows: 2 dirs * T*B
#define ROWS_E 64          // encoder combined rows: 2 dirs * B
#define PDT 66             // padded t-dim for decoder proj (t=64 -> <PART>, t=65 pad)
#define PDROWS (PDT*BB)    // 2112 per dir (divisible by 64)
#define NVT 63             // vocab tiles of 128 (63*128 = 8064 >= 8000)

// ----- scratch (device globals; allocation-free) -----
__device__ float d_Xe[TT*ROWS_E*GG];          // encoder input proj (incl bias)
__device__ float d_Henc[2*(TT+1)*BB*HH];      // encoder hidden, slot 0 = zeros
__device__ float d_Cenc[2*ROWS_E*HH];         // encoder cell ping-pong
__device__ float d_Pd[2*PDROWS*GG];           // decoder per-position input proj (incl bias)
__device__ float d_Hdec[5*NDROW*HH];          // decoder hidden: slot0=h0, slot s+1 = step s out
__device__ float d_Cdec[2*NDROW*HH];          // decoder cell ping-pong
__device__ int   d_tokE[TT*ROWS_E];
__device__ int   d_tokD[2*PDROWS];
__device__ float d_zc[3*NDROW];               // char-pick logits
__device__ float d_zt[4*NDROW];               // <PART>-pick logits (s=1..3 used)
__device__ float d_part[4*NDROW*NVT*2];       // (max, sumexp) partials per v-tile
__device__ float d_lse[4*NDROW];
__device__ float d_res[2*TT*WW*BB];           // segment log-probs per dir

__device__ __forceinline__ float sigm(float x){ return 1.f/(1.f+__expf(-x)); }

// ----- init: zero states, build token tables -----
__global__ void k_init(const int* __restrict__ sent){
    int i = blockIdx.x*blockDim.x + threadIdx.x;   // 32768 threads
    if (i < 2*BB*HH){                               // zero Henc slot 0, both dirs
        int dir = i/(BB*HH); int rem = i%(BB*HH);
        d_Henc[(dir*(TT+1))*BB*HH + rem] = 0.f;
    }
    if (i < ROWS_E*HH) d_Cenc[i] = 0.f;             // zero cell ping slot 0
    if (i < TT*ROWS_E){                             // encoder tokens: <PART> + vec[:, :-1]
        int t = i/ROWS_E, r = i%ROWS_E, dir = r/BB, b = r%BB;
        int tok = (t==0) ? 0 : (dir ? sent[b*TT + (TT-t)] : sent[b*TT + (t-1)]);
        d_tokE[i] = tok;
    }
    if (i < 2*PDROWS){                              // decoder per-position tokens (+PART slot)
        int dir = i/PDROWS; int rem = i%PDROWS; int t = rem/BB, b = rem%BB;
        int tok = (t < TT) ? (dir ? sent[b*TT + (TT-1-t)] : sent[b*TT + t]) : 0;
        d_tokD[i] = tok;
    }
}

// ----- gathered NT GEMM: out[m][g] = emb[tok[m]] . W[g] + bias[g]  (K=256) -----
__global__ void __launch_bounds__(256) k_proj(int mode, const float* __restrict__ emb,
    const float* __restrict__ Wa, const float* __restrict__ Wb,
    const float* __restrict__ ba, const float* __restrict__ bb2)
{
    __shared__ float As[16][68];
    __shared__ float Bs[16][68];
    const int* tok = mode ? d_tokD : d_tokE;
    float* out     = mode ? d_Pd   : d_Xe;
    int m0 = blockIdx.x*64, n0 = blockIdx.y*64;
    const float* Wt = Wa; const float* bt = ba;
    if (mode && m0 >= PDROWS){ Wt = Wb; bt = bb2; }
    int t = threadIdx.x; int tx = t%16, ty = t/16;
    float acc[4][4]; 
    #pragma unroll
    for(int i=0;i<4;i++){ 
        #pragma unroll
        for(int j=0;j<4;j++) acc[i][j]=0.f; }
    for (int k0=0; k0<EE; k0+=16){
        #pragma unroll
        for (int i=0;i<4;i++){
            int e = t + 256*i; int mm = e>>4, kk = e&15;
            As[kk][mm] = emb[tok[m0+mm]*EE + k0+kk];
            Bs[kk][mm] = Wt[(n0+mm)*EE + k0+kk];
        }
        __syncthreads();
        #pragma unroll
        for (int k=0;k<16;k++){
            float a[4], b[4];
            #pragma unroll
            for(int i=0;i<4;i++) a[i]=As[k][ty*4+i];
            #pragma unroll
            for(int j=0;j<4;j++) b[j]=Bs[k][tx*4+j];
            #pragma unroll
            for(int i=0;i<4;i++)
                #pragma unroll
                for(int j=0;j<4;j++) acc[i][j] = fmaf(a[i], b[j], acc[i][j]);
        }
        __syncthreads();
    }
    #pragma unroll
    for(int i=0;i<4;i++){ int m = m0 + ty*4+i;
        #pragma unroll
        for(int j=0;j<4;j++){ int n = n0 + tx*4+j;
            out[m*GG + n] = acc[i][j] + bt[n];
        }
    }
}

// ----- encoder step t: gates = Xe[t] + H_{t} @ Whh^T ; fused LSTM cell -----
__global__ void __launch_bounds__(256) k_encstep(const float* __restrict__ Whh, int t){
    __shared__ float Hs[16][ROWS_E+1];
    __shared__ float Ws[16][33];
    const int h0 = blockIdx.x*8;      // 64 blocks, 8 h-indices each (x4 gates = 32 cols)
    const int tid = threadIdx.x;
    const int r = tid & 63, hq = tid >> 6;
    float acc[8];
    #pragma unroll
    for(int i=0;i<8;i++) acc[i]=0.f;
    for (int k0=0; k0<HH; k0+=16){
        #pragma unroll
        for (int i=0;i<4;i++){
            int e = tid + 256*i; int rr = e>>4, kk = e&15;
            int dir = rr>>5, b = rr&31;
            Hs[kk][rr] = d_Henc[((dir*(TT+1)+t)*BB+b)*HH + k0+kk];
        }
        #pragma unroll
        for (int i=0;i<2;i++){
            int e = tid + 256*i; int c = e>>4, kk = e&15;
            Ws[kk][c] = Whh[((c>>3)*HH + h0 + (c&7))*HH + k0+kk];
        }
        __syncthreads();
        #pragma unroll
        for (int k=0;k<16;k++){
            float a = Hs[k][r];
            #pragma unroll
            for(int j=0;j<2;j++)
                #pragma unroll
                for(int g=0;g<4;g++)
                    acc[j*4+g] = fmaf(a, Ws[k][g*8 + hq*2 + j], acc[j*4+g]);
        }
        __syncthreads();
    }
    const float* xrow = d_Xe + (t*ROWS_E + r)*GG;
    const int dir = r>>5, b = r&31;
    #pragma unroll
    for(int j=0;j<2;j++){
        int h = h0 + hq*2 + j;
        float gi = acc[j*4+0] + xrow[h];
        float gf = acc[j*4+1] + xrow[HH+h];
        float gg = acc[j*4+2] + xrow[2*HH+h];
        float go = acc[j*4+3] + xrow[3*HH+h];
        float cp = d_Cenc[(t&1)*ROWS_E*HH + r*HH + h];
        float c  = sigm(gf)*cp + sigm(gi)*tanhf(gg);
        float hn = sigm(go)*tanhf(c);
        d_Cenc[((t+1)&1)*ROWS_E*HH + r*HH + h] = c;
        d_Henc[((dir*(TT+1)+(t+1))*BB+b)*HH + h] = hn;
    }
}

// ----- decoder init: h0 = c0 = encoder hidden at segment start -----
__global__ void k_decinit(){
    int i = blockIdx.x*blockDim.x + threadIdx.x;    // NDROW*HH threads
    int row = i>>9, h = i&511;
    int dir = row>>11, rr = row&2047, m = rr>>5, b = rr&31;
    float v = d_Henc[((dir*(TT+1)+(m+1))*BB+b)*HH + h];
    d_Hdec[i] = v;
    d_Cdec[i] = v;
}

// ----- decoder step s (4096 rows, per-dir weights), fused LSTM cell -----
__global__ void __launch_bounds__(256) k_decstep(const float* __restrict__ fWhh,
                                                 const float* __restrict__ bWhh, int s){
    __shared__ float Hs[16][65];
    __shared__ float Ws[16][33];
    const int h0 = blockIdx.x*8;
    const int rt = blockIdx.y*64;
    const int dir = rt >= 2048;
    const float* Whh = dir ? bWhh : fWhh;
    const float* Hprev = d_Hdec + s*NDROW*HH;
    const int tid = threadIdx.x;
    const int r = tid & 63, hq = tid >> 6;
    float acc[8];
    #pragma unroll
    for(int i=0;i<8;i++) acc[i]=0.f;
    for (int k0=0; k0<HH; k0+=16){
        #pragma unroll
        for (int i=0;i<4;i++){
            int e = tid + 256*i; int rr = e>>4, kk = e&15;
            Hs[kk][rr] = Hprev[(rt+rr)*HH + k0+kk];
        }
        #pragma unroll
        for (int i=0;i<2;i++){
            int e = tid + 256*i; int c = e>>4, kk = e&15;
            Ws[kk][c] = Whh[((c>>3)*HH + h0 + (c&7))*HH + k0+kk];
        }
        __syncthreads();
        #pragma unroll
        for (int k=0;k<16;k++){
            float a = Hs[k][r];
            #pragma unroll
            for(int j=0;j<2;j++)
                #pragma unroll
                for(int g=0;g<4;g++)
                    acc[j*4+g] = fmaf(a, Ws[k][g*8 + hq*2 + j], acc[j*4+g]);
        }
        __syncthreads();
    }
    const int row = rt + r;
    const int rr2 = row - dir*2048; const int m = rr2>>5; const int b = rr2&31;
    const int tp = (s==0) ? TT : min(m+s-1, TT-1);    // PART slot at t=TT
    const float* xrow = d_Pd + ((dir*PDT + tp)*BB + b)*GG;
    #pragma unroll
    for(int j=0;j<2;j++){
        int h = h0 + hq*2 + j;
        float gi = acc[j*4+0] + xrow[h];
        float gf = acc[j*4+1] + xrow[HH+h];
        float gg = acc[j*4+2] + xrow[2*HH+h];
        float go = acc[j*4+3] + xrow[3*HH+h];
        float cp = d_Cdec[(s&1)*NDROW*HH + row*HH + h];
        float c  = sigm(gf)*cp + sigm(gi)*tanhf(gg);
        float hn = sigm(go)*tanhf(c);
        d_Cdec[((s+1)&1)*NDROW*HH + row*HH + h] = c;
        d_Hdec[(s+1)*NDROW*HH + row*HH + h] = hn;
    }
}

// ----- gathered single logits (char target + <PART>), warp per dot -----
__global__ void k_picks(const float* __restrict__ fhW, const float* __restrict__ bhW,
                        const float* __restrict__ fhb, const float* __restrict__ bhb){
    int w = (blockIdx.x*blockDim.x + threadIdx.x) >> 5;
    int lane = threadIdx.x & 31;
    if (w >= 6*NDROW) return;
    int kind = w / NDROW;            // 0..2: char pick s=kind ; 3..5: PART pick s=kind-2
    int row  = w % NDROW;
    int dir = row>>11, rr = row&2047, m = rr>>5, b = rr&31;
    const float* hW = dir ? bhW : fhW;
    const float* hb = dir ? bhb : fhb;
    int s, y;
    if (kind < 3){ s = kind;   y = d_tokD[dir*PDROWS + min(m+s, TT-1)*BB + b]; }
    else         { s = kind-2; y = 0; }
    const float* h = d_Hdec + (s+1)*NDROW*HH + row*HH;
    const float* wv = hW + y*HH;
    float sum = 0.f;
    for (int k=lane; k<HH; k+=32) sum += h[k]*wv[k];
    #pragma unroll
    for (int off=16; off; off>>=1) sum += __shfl_xor_sync(0xffffffffu, sum, off);
    if (!lane){
        if (kind < 3) d_zc[s*NDROW + row] = sum + hb[y];
        else          d_zt[s*NDROW + row] = sum + hb[0];
    }
}

// ----- big GEMM + fused partial logsumexp: z = Hdec[s] @ hW^T + hb -----
__global__ void __launch_bounds__(256) k_lse1(const float* __restrict__ fhW,
    const float* __restrict__ bhW, const float* __restrict__ fhb, const float* __restrict__ bhb)
{
    __shared__ __align__(16) float As[16][132];
    __shared__ __align__(16) float Bs[16][132];
    const int s  = blockIdx.z;
    const int rt = blockIdx.y*128;
    const int v0 = blockIdx.x*128;
    const int dir = rt >= 2048;
    const float* A  = d_Hdec + (s+1)*NDROW*HH + rt*HH;
    const float* Wv = dir ? bhW : fhW;
    const float* hb = dir ? bhb : fhb;
    const int t = threadIdx.x; const int tx = t%16, ty = t/16;
    const int lm = t>>1, lk = (t&1)*8;
    float acc[8][8];
    #pragma unroll
    for(int i=0;i<8;i++)
        #pragma unroll
        for(int j=0;j<8;j++) acc[i][j]=0.f;

    for (int k0=0; k0<HH; k0+=16){
        const float* Ar = A + lm*HH + k0 + lk;
        float4 a0 = *(const float4*)(Ar);
        float4 a1 = *(const float4*)(Ar+4);
        As[lk+0][lm]=a0.x; As[lk+1][lm]=a0.y; As[lk+2][lm]=a0.z; As[lk+3][lm]=a0.w;
        As[lk+4][lm]=a1.x; As[lk+5][lm]=a1.y; As[lk+6][lm]=a1.z; As[lk+7][lm]=a1.w;
        int v = v0 + lm;
        float4 b0 = make_float4(0.f,0.f,0.f,0.f), b1 = make_float4(0.f,0.f,0.f,0.f);
        if (v < VV){
            const float* Br = Wv + v*HH + k0 + lk;
            b0 = *(const float4*)(Br); b1 = *(const float4*)(Br+4);
        }
        Bs[lk+0][lm]=b0.x; Bs[lk+1][lm]=b0.y; Bs[lk+2][lm]=b0.z; Bs[lk+3][lm]=b0.w;
        Bs[lk+4][lm]=b1.x; Bs[lk+5][lm]=b1.y; Bs[lk+6][lm]=b1.z; Bs[lk+7][lm]=b1.w;
        __syncthreads();
        #pragma unroll
        for (int k=0;k<16;k++){
            float4 x0 = *(const float4*)&As[k][ty*8];
            float4 x1 = *(const float4*)&As[k][ty*8+4];
            float4 y0 = *(const float4*)&Bs[k][tx*8];
            float4 y1 = *(const float4*)&Bs[k][tx*8+4];
            float av[8] = {x0.x,x0.y,x0.z,x0.w,x1.x,x1.y,x1.z,x1.w};
            float bv[8] = {y0.x,y0.y,y0.z,y0.w,y1.x,y1.y,y1.z,y1.w};
            #pragma unroll
            for(int i=0;i<8;i++)
                #pragma unroll
                for(int j=0;j<8;j++) acc[i][j] = fmaf(av[i], bv[j], acc[i][j]);
        }
        __syncthreads();
    }
    // fused partial LSE per row over this 128-v tile (16-lane shfl reduce)
    #pragma unroll
    for (int i=0;i<8;i++){
        int row = rt + ty*8 + i;
        float z[8]; float mx = -INFINITY;
        #pragma unroll
        for (int j=0;j<8;j++){
            int v = v0 + tx*8 + j;
            z[j] = (v < VV) ? (acc[i][j] + hb[v]) : -INFINITY;
            mx = fmaxf(mx, z[j]);
        }
        #pragma unroll
        for (int off=8; off; off>>=1) mx = fmaxf(mx, __shfl_xor_sync(0xffffffffu, mx, off, 16));
        float sm = 0.f;
        #pragma unroll
        for (int j=0;j<8;j++) sm += __expf(z[j]-mx);
        #pragma unroll
        for (int off=8; off; off>>=1) sm += __shfl_xor_sync(0xffffffffu, sm, off, 16);
        if (tx == 0){
            int idx = ((s*NDROW + row)*NVT + blockIdx.x)*2;
            d_part[idx] = mx; d_part[idx+1] = sm;
        }
    }
}

__global__ void k_lse2(){
    int i = blockIdx.x*blockDim.x + threadIdx.x;     // 4*NDROW
    if (i >= 4*NDROW) return;
    int base = i*NVT*2;
    float mx = -INFINITY;
    for (int vb=0; vb<NVT; vb++) mx = fmaxf(mx, d_part[base+vb*2]);
    float sm = 0.f;
    for (int vb=0; vb<NVT; vb++) sm += d_part[base+vb*2+1]*__expf(d_part[base+vb*2]-mx);
    d_lse[i] = mx + logf(sm);
}

// ----- segment scores: res[l] = cumsum(char_lp) + tag_lp[l+1] -----
__global__ void k_res(){
    int i = blockIdx.x*blockDim.x + threadIdx.x;
    if (i >= NDROW) return;
    int dir = i>>11, rr = i&2047, m = rr>>5, b = rr&31;
    float cum = 0.f;
    #pragma unroll
    for (int l=0; l<WW; l++){
        cum += d_zc[l*NDROW+i] - d_lse[l*NDROW+i];
        float tg = d_zt[(l+1)*NDROW+i] - d_lse[(l+1)*NDROW+i];
        d_res[((dir*TT+m)*WW+l)*BB + b] = cum + tg;
    }
}

// ----- bidirectional combine + semi-Markov DP + mean -----
__global__ void k_final(float* __restrict__ out){
    int b = threadIdx.x;                  // 32 threads, one per batch
    float w0 = 0.f, w1 = NEGF, w2 = NEGF;
    for (int e=0; e<TT; e++){
        float p[3];
        #pragma unroll
        for (int l=0; l<3; l++){
            int st = e - l;
            if (st >= 0)
                p[l] = d_res[((0*TT+st)*WW+l)*BB + b]
                     + d_res[((1*TT+(TT-1-e))*WW+l)*BB + b];
            else p[l] = NEGF;
        }
        float x0 = w0+p[0], x1 = w1+p[1], x2 = w2+p[2];
        float m = fmaxf(x0, fmaxf(x1, x2));
        float tot = m + logf(__expf(x0-m) + __expf(x1-m) + __expf(x2-m));
        w2 = w1; w1 = w0; w0 = tot;
    }
    float v = w0;
    #pragma unroll
    for (int off=16; off; off>>=1) v += __shfl_xor_sync(0xffffffffu, v, off);
    if (b == 0) out[0] = -v/(float)BB;
}

extern "C" void kernel_launch(void* const* d_in, const int* in_sizes, int n_in,
                              void* d_out, int out_size){
    const int*   sent = (const int*)  d_in[0];
    const float* emb  = (const float*)d_in[1];
    const float* eWih = (const float*)d_in[2];
    const float* eWhh = (const float*)d_in[3];
    const float* eB   = (const float*)d_in[4];
    const float* fWih = (const float*)d_in[5];
    const float* fWhh = (const float*)d_in[6];
    const float* fB   = (const float*)d_in[7];
    const float* fhW  = (const float*)d_in[8];
    const float* fhb  = (const float*)d_in[9];
    const float* bWih = (const float*)d_in[10];
    const float* bWhh = (const float*)d_in[11];
    const float* bB   = (const float*)d_in[12];
    const float* bhW  = (const float*)d_in[13];
    const float* bhb  = (const float*)d_in[14];
    float* out = (float*)d_out;

    k_init<<<128,256>>>(sent);
    k_proj<<<dim3(64,32),256>>>(0, emb, eWih, eWih, eB, eB);
    k_proj<<<dim3(66,32),256>>>(1, emb, fWih, bWih, fB, bB);
    for (int t=0; t<TT; t++) k_encstep<<<64,256>>>(eWhh, t);
    k_decinit<<<8192,256>>>();
    for (int s=0; s<4; s++) k_decstep<<<dim3(64,64),256>>>(fWhh, bWhh, s);
    k_picks<<<3072,256>>>(fhW, bhW, fhb, bhb);
    k_lse1<<<dim3(NVT,32,4),256>>>(fhW, bhW, fhb, bhb);
    k_lse2<<<64,256>>>();
    k_res<<<16,256>>>();
    k_final<<<1,32>>>(out);
}

// round 2
// speedup vs baseline: 2.6431x; 2.6431x over previous
#include <cuda_runtime.h>
#include <math.h>

#define BB 32
#define TT 64
#define VV 8000
#define EE 256
#define HH 512
#define GG 2048
#define WW 3
#define NEGF (-1e30f)
#define NDROW 4096
#define ROWS_E 64
#define PDT 68
#define PDROWS (PDT*BB)      // 2176 (17*128, tile-aligned)
#define NP 250               // vocab partials of width 32
#define SR (4*NDROW)

// ----- scratch -----
__device__ float d_Xe[TT*ROWS_E*GG];
__device__ float d_Henc[2*(TT+1)*BB*HH];
__device__ float d_Pd[2*PDROWS*GG];
__device__ float d_G[NDROW*GG];
__device__ float d_Hdec[5*NDROW*HH];
__device__ float d_Cdec[2*NDROW*HH];
__device__ int   d_tokE[TT*ROWS_E];
__device__ int   d_tokD[2*PDROWS];
__device__ float d_zc[3*NDROW];
__device__ float d_zt[4*NDROW];
__device__ float d_part[NP*SR*2];
__device__ float d_lse[4*NDROW];
__device__ float d_res[2*TT*WW*BB];
__device__ unsigned g_cnt;
__device__ unsigned g_gen;

__device__ __forceinline__ float sigm(float x){ return 1.f/(1.f+__expf(-x)); }

// ----- init -----
__global__ void k_init(const int* __restrict__ sent){
    int i = blockIdx.x*blockDim.x + threadIdx.x;   // 32768 threads
    if (i == 0){ g_cnt = 0u; g_gen = 0u; }
    if (i < 2*BB*HH){
        int dir = i/(BB*HH); int rem = i%(BB*HH);
        d_Henc[(dir*(TT+1))*BB*HH + rem] = 0.f;
    }
    if (i < TT*ROWS_E){
        int t = i/ROWS_E, r = i%ROWS_E, dir = r/BB, b = r%BB;
        int tok = (t==0) ? 0 : (dir ? sent[b*TT + (TT-t)] : sent[b*TT + (t-1)]);
        d_tokE[i] = tok;
    }
    if (i < 2*PDROWS){
        int dir = i/PDROWS; int rem = i%PDROWS; int t = rem/BB, b = rem%BB;
        int tok = (t < TT) ? (dir ? sent[b*TT + (TT-1-t)] : sent[b*TT + t]) : 0;
        d_tokD[i] = tok;
    }
}

// ===================== generic tf32 mma GEMM =====================
// C(128x128 tile) = A(Mx K) * B^T(N x K), fused epilogue by MODE.
// MODE 0: A = emb[tok[m]], K=256, out = Xe/Pd, +bias
// MODE 1: A = d_Hdec[s],  K=512, out = d_G,   +Pd x-row
// MODE 2: A = d_Hdec[s+1],K=512, partial LSE over 32-wide vocab strips
__device__ __forceinline__ void mma8(float* c, const unsigned* a, const unsigned* b){
    asm volatile("mma.sync.aligned.m16n8k8.row.col.f32.tf32.tf32.f32 "
        "{%0,%1,%2,%3},{%4,%5,%6,%7},{%8,%9},{%0,%1,%2,%3};\n"
        : "+f"(c[0]),"+f"(c[1]),"+f"(c[2]),"+f"(c[3])
        : "r"(a[0]),"r"(a[1]),"r"(a[2]),"r"(a[3]),"r"(b[0]),"r"(b[1]));
}

template<int MODE>
__global__ void __launch_bounds__(256) k_gemm(
    const float* __restrict__ emb,
    const float* __restrict__ B0, const float* __restrict__ B1,
    const float* __restrict__ bias0, const float* __restrict__ bias1,
    int gsel, int mhalf, int s)
{
    constexpr int KD = (MODE==0)? EE : HH;
    constexpr int NT = KD/16;
    __shared__ float sA[128*20];
    __shared__ float sB[128*20];
    const int tid = threadIdx.x;
    const int m0 = blockIdx.y*128;
    const int n0 = blockIdx.x*128;
    const int ss = (MODE==2)? (int)blockIdx.z : s;
    const int dir = (m0 >= mhalf) ? 1 : 0;
    const float* Bm   = dir? B1 : B0;
    const float* bias = dir? bias1 : bias0;

    const float* Aptr = 0;
    const int* tok = 0;
    if (MODE==0) tok = gsel? d_tokD : d_tokE;
    else if (MODE==1) Aptr = d_Hdec + ss*NDROW*HH;
    else Aptr = d_Hdec + (ss+1)*NDROW*HH;

    const int lrow = tid>>1, lko = (tid&1)*8;
    const float* arow = (MODE==0)? (emb + (long)tok[m0+lrow]*KD) : (Aptr + (long)(m0+lrow)*KD);
    const int vrow = n0 + lrow;
    const bool bval = (MODE!=2) || (vrow < VV);
    const float* brow = Bm + (long)(bval? vrow : 0)*KD;

    float4 pa0, pa1, pb0, pb1;
    pa0 = *(const float4*)(arow + lko);
    pa1 = *(const float4*)(arow + lko + 4);
    if (bval){ pb0 = *(const float4*)(brow + lko); pb1 = *(const float4*)(brow + lko + 4); }
    else { pb0 = make_float4(0,0,0,0); pb1 = pb0; }

    const int lane = tid&31, warp = tid>>5;
    const int wm = warp&1, wn = warp>>1;
    const int g = lane>>2, t4 = lane&3;
    float acc[4][4][4];
    #pragma unroll
    for (int i=0;i<4;i++)
        #pragma unroll
        for (int j=0;j<4;j++)
            #pragma unroll
            for (int e=0;e<4;e++) acc[i][j][e]=0.f;

    for (int kt=0; kt<NT; kt++){
        __syncthreads();
        {
            float* pA = sA + lrow*20 + lko;
            *(float4*)pA = pa0; *(float4*)(pA+4) = pa1;
            float* pB = sB + lrow*20 + lko;
            *(float4*)pB = pb0; *(float4*)(pB+4) = pb1;
        }
        __syncthreads();
        if (kt+1 < NT){
            int k0 = (kt+1)*16;
            pa0 = *(const float4*)(arow + k0 + lko);
            pa1 = *(const float4*)(arow + k0 + lko + 4);
            if (bval){
                pb0 = *(const float4*)(brow + k0 + lko);
                pb1 = *(const float4*)(brow + k0 + lko + 4);
            }
        }
        #pragma unroll
        for (int ks=0; ks<16; ks+=8){
            unsigned a[4][4], b[4][2];
            #pragma unroll
            for (int mf=0; mf<4; mf++){
                const float* base = sA + (wm*64+mf*16)*20 + ks + t4;
                a[mf][0] = __float_as_uint(base[g*20]);
                a[mf][1] = __float_as_uint(base[(g+8)*20]);
                a[mf][2] = __float_as_uint(base[g*20+4]);
                a[mf][3] = __float_as_uint(base[(g+8)*20+4]);
            }
            #pragma unroll
            for (int nf=0; nf<4; nf++){
                const float* base = sB + (wn*32+nf*8+g)*20 + ks + t4;
                b[nf][0] = __float_as_uint(base[0]);
                b[nf][1] = __float_as_uint(base[4]);
            }
            #pragma unroll
            for (int mf=0; mf<4; mf++)
                #pragma unroll
                for (int nf=0; nf<4; nf++)
                    mma8(acc[mf][nf], a[mf], b[nf]);
        }
    }

    // ---- epilogues ----
    if (MODE==0){
        float* Co = gsel? d_Pd : d_Xe;
        #pragma unroll
        for (int mf=0; mf<4; mf++)
            #pragma unroll
            for (int lohi=0; lohi<2; lohi++){
                int r = m0 + wm*64 + mf*16 + g + lohi*8;
                #pragma unroll
                for (int nf=0; nf<4; nf++){
                    int col = n0 + wn*32 + nf*8 + 2*t4;
                    float2 o;
                    o.x = acc[mf][nf][lohi*2+0] + bias[col];
                    o.y = acc[mf][nf][lohi*2+1] + bias[col+1];
                    *(float2*)&Co[(long)r*GG + col] = o;
                }
            }
    } else if (MODE==1){
        #pragma unroll
        for (int mf=0; mf<4; mf++)
            #pragma unroll
            for (int lohi=0; lohi<2; lohi++){
                int r = m0 + wm*64 + mf*16 + g + lohi*8;
                int rr = r - dir*2048;
                int m = rr>>5, b2 = rr&31;
                int tp = (ss==0)? TT : min(m+ss-1, TT-1);
                const float* xr = d_Pd + ((long)(dir*PDT+tp)*BB + b2)*GG;
                #pragma unroll
                for (int nf=0; nf<4; nf++){
                    int col = n0 + wn*32 + nf*8 + 2*t4;
                    float2 o;
                    o.x = acc[mf][nf][lohi*2+0] + xr[col];
                    o.y = acc[mf][nf][lohi*2+1] + xr[col+1];
                    *(float2*)&d_G[(long)r*GG + col] = o;
                }
            }
    } else {
        int nb = (n0>>5) + wn;
        #pragma unroll
        for (int mf=0; mf<4; mf++)
            #pragma unroll
            for (int lohi=0; lohi<2; lohi++){
                int r = m0 + wm*64 + mf*16 + g + lohi*8;
                float z[8]; float mx = NEGF;
                #pragma unroll
                for (int nf=0; nf<4; nf++)
                    #pragma unroll
                    for (int e=0; e<2; e++){
                        int v = n0 + wn*32 + nf*8 + 2*t4 + e;
                        float zz = acc[mf][nf][lohi*2+e] + ((v<VV)? bias[v] : NEGF);
                        z[nf*2+e] = zz;
                        mx = fmaxf(mx, zz);
                    }
                mx = fmaxf(mx, __shfl_xor_sync(0xffffffffu, mx, 1));
                mx = fmaxf(mx, __shfl_xor_sync(0xffffffffu, mx, 2));
                float sm = 0.f;
                #pragma unroll
                for (int j=0;j<8;j++) sm += __expf(z[j]-mx);
                sm += __shfl_xor_sync(0xffffffffu, sm, 1);
                sm += __shfl_xor_sync(0xffffffffu, sm, 2);
                if (t4==0 && nb < NP){
                    int srow = ss*NDROW + r;
                    d_part[((long)nb*SR + srow)*2    ] = mx;
                    d_part[((long)nb*SR + srow)*2 + 1] = sm;
                }
            }
    }
}

// ===================== persistent encoder =====================
// 128 blocks x 256 threads; thread owns one (row r, hidden h) pair.
// Whh slice cached in smem; cell state in register; grid barrier per step.
__global__ void __launch_bounds__(256) k_enc(const float* __restrict__ Whh){
    __shared__ float Ws[HH*16];
    __shared__ float Hs[32*65];
    const int tid = threadIdx.x;
    const int r = tid & 63, q = tid >> 6;
    const int h = blockIdx.x*4 + q;
    const int dir = r >> 5, b = r & 31;
    {   // one-time weight load: Ws[k*16 + (qq*4+gg)] = Whh[gg*H + bid*4+qq][k]
        int c = tid >> 4;
        int gg = c & 3, qq = c >> 2;
        const float* wr = Whh + ((long)(gg*HH + blockIdx.x*4 + qq))*HH;
        #pragma unroll 4
        for (int j=0;j<32;j++){
            int k = (tid & 15) + j*16;
            Ws[k*16 + c] = wr[k];
        }
    }
    const int srow = tid >> 2, koff = (tid & 3)*8;
    const int sdir = srow >> 5, sb = srow & 31;
    unsigned gen = 0;
    float creg = 0.f;
    __syncthreads();
    for (int t=0; t<TT; t++){
        float a0=0.f,a1=0.f,a2=0.f,a3=0.f;
        const float* Hsrc = d_Henc + ((long)(sdir*(TT+1)+t)*BB + sb)*HH;
        float4 p0 = *(const float4*)(Hsrc + koff);
        float4 p1 = *(const float4*)(Hsrc + koff + 4);
        for (int kt=0; kt<16; kt++){
            __syncthreads();
            float* hp = Hs + koff*65 + srow;
            hp[0]=p0.x; hp[65]=p0.y; hp[130]=p0.z; hp[195]=p0.w;
            hp[260]=p1.x; hp[325]=p1.y; hp[390]=p1.z; hp[455]=p1.w;
            __syncthreads();
            if (kt < 15){
                p0 = *(const float4*)(Hsrc + (kt+1)*32 + koff);
                p1 = *(const float4*)(Hsrc + (kt+1)*32 + koff + 4);
            }
            #pragma unroll
            for (int k=0;k<32;k++){
                float a = Hs[k*65 + r];
                float4 w = *(const float4*)&Ws[((kt<<5)+k)*16 + (q<<2)];
                a0 = fmaf(a, w.x, a0); a1 = fmaf(a, w.y, a1);
                a2 = fmaf(a, w.z, a2); a3 = fmaf(a, w.w, a3);
            }
        }
        const float* xr = d_Xe + (long)(t*ROWS_E + r)*GG;
        float gi = a0 + xr[h], gf = a1 + xr[HH+h];
        float g2 = a2 + xr[2*HH+h], go = a3 + xr[3*HH+h];
        creg = sigm(gf)*creg + sigm(gi)*tanhf(g2);
        float hn = sigm(go)*tanhf(creg);
        d_Henc[((long)(dir*(TT+1)+(t+1))*BB + b)*HH + h] = hn;
        // grid barrier
        __threadfence();
        __syncthreads();
        if (tid==0){
            unsigned a = atomicAdd(&g_cnt, 1u);
            if (a == gridDim.x-1){
                g_cnt = 0;
                __threadfence();
                atomicExch(&g_gen, gen+1u);
            } else {
                while (*((volatile unsigned*)&g_gen) != gen+1u) __nanosleep(32);
                __threadfence();
            }
        }
        __syncthreads();
        gen++;
    }
}

// ----- decoder init -----
__global__ void k_decinit(){
    int i = blockIdx.x*blockDim.x + threadIdx.x;
    int row = i>>9, h = i&511;
    int dir = row>>11, rr = row&2047, m = rr>>5, b = rr&31;
    float v = d_Henc[((long)(dir*(TT+1)+(m+1))*BB+b)*HH + h];
    d_Hdec[i] = v;
    d_Cdec[i] = v;
}

// ----- decoder cell (gates precomputed in d_G) -----
__global__ void k_cell(int s){
    int i = blockIdx.x*blockDim.x + threadIdx.x;
    int row = i>>9, h = i&511;
    const float* gr = d_G + (long)row*GG;
    float gi = gr[h], gf = gr[HH+h], g2 = gr[2*HH+h], go = gr[3*HH+h];
    float cp = d_Cdec[(s&1)*NDROW*HH + i];
    float c = sigm(gf)*cp + sigm(gi)*tanhf(g2);
    float hn = sigm(go)*tanhf(c);
    d_Cdec[((s+1)&1)*NDROW*HH + i] = c;
    d_Hdec[(s+1)*NDROW*HH + i] = hn;
}

// ----- gathered single logits (char target + <PART>) -----
__global__ void k_picks(const float* __restrict__ fhW, const float* __restrict__ bhW,
                        const float* __restrict__ fhb, const float* __restrict__ bhb){
    int w = (blockIdx.x*blockDim.x + threadIdx.x) >> 5;
    int lane = threadIdx.x & 31;
    if (w >= 6*NDROW) return;
    int kind = w / NDROW;
    int row  = w % NDROW;
    int dir = row>>11, rr = row&2047, m = rr>>5, b = rr&31;
    const float* hW = dir ? bhW : fhW;
    const float* hb = dir ? bhb : fhb;
    int s, y;
    if (kind < 3){ s = kind;   y = d_tokD[dir*PDROWS + min(m+s, TT-1)*BB + b]; }
    else         { s = kind-2; y = 0; }
    const float* h = d_Hdec + (long)(s+1)*NDROW*HH + (long)row*HH;
    const float* wv = hW + (long)y*HH;
    float sum = 0.f;
    #pragma unroll 4
    for (int k=lane; k<HH; k+=32) sum += h[k]*wv[k];
    #pragma unroll
    for (int off=16; off; off>>=1) sum += __shfl_xor_sync(0xffffffffu, sum, off);
    if (!lane){
        if (kind < 3) d_zc[s*NDROW + row] = sum + hb[y];
        else          d_zt[s*NDROW + row] = sum + hb[0];
    }
}

// ----- combine LSE partials (online) -----
__global__ void k_lse2(){
    int i = blockIdx.x*blockDim.x + threadIdx.x;
    if (i >= SR) return;
    float mx = NEGF, sm = 0.f;
    for (int nb=0; nb<NP; nb++){
        float2 p = *(float2*)&d_part[((long)nb*SR + i)*2];
        if (p.x > mx){ sm = sm*__expf(mx-p.x) + p.y; mx = p.x; }
        else sm += p.y*__expf(p.x-mx);
    }
    d_lse[i] = mx + logf(sm);
}

// ----- segment scores -----
__global__ void k_res(){
    int i = blockIdx.x*blockDim.x + threadIdx.x;
    if (i >= NDROW) return;
    int dir = i>>11, rr = i&2047, m = rr>>5, b = rr&31;
    float cum = 0.f;
    #pragma unroll
    for (int l=0; l<WW; l++){
        cum += d_zc[l*NDROW+i] - d_lse[l*NDROW+i];
        float tg = d_zt[(l+1)*NDROW+i] - d_lse[(l+1)*NDROW+i];
        d_res[((dir*TT+m)*WW+l)*BB + b] = cum + tg;
    }
}

// ----- final DP -----
__global__ void k_final(float* __restrict__ out){
    int b = threadIdx.x;
    float w0 = 0.f, w1 = NEGF, w2 = NEGF;
    for (int e=0; e<TT; e++){
        float p[3];
        #pragma unroll
        for (int l=0; l<3; l++){
            int st = e - l;
            p[l] = (st >= 0) ? (d_res[((0*TT+st)*WW+l)*BB + b]
                              + d_res[((1*TT+(TT-1-e))*WW+l)*BB + b]) : NEGF;
        }
        float x0 = w0+p[0], x1 = w1+p[1], x2 = w2+p[2];
        float m = fmaxf(x0, fmaxf(x1, x2));
        float tot = m + logf(__expf(x0-m) + __expf(x1-m) + __expf(x2-m));
        w2 = w1; w1 = w0; w0 = tot;
    }
    float v = w0;
    #pragma unroll
    for (int off=16; off; off>>=1) v += __shfl_xor_sync(0xffffffffu, v, off);
    if (b == 0) out[0] = -v/(float)BB;
}

extern "C" void kernel_launch(void* const* d_in, const int* in_sizes, int n_in,
                              void* d_out, int out_size){
    const int*   sent = (const int*)  d_in[0];
    const float* emb  = (const float*)d_in[1];
    const float* eWih = (const float*)d_in[2];
    const float* eWhh = (const float*)d_in[3];
    const float* eB   = (const float*)d_in[4];
    const float* fWih = (const float*)d_in[5];
    const float* fWhh = (const float*)d_in[6];
    const float* fB   = (const float*)d_in[7];
    const float* fhW  = (const float*)d_in[8];
    const float* fhb  = (const float*)d_in[9];
    const float* bWih = (const float*)d_in[10];
    const float* bWhh = (const float*)d_in[11];
    const float* bB   = (const float*)d_in[12];
    const float* bhW  = (const float*)d_in[13];
    const float* bhb  = (const float*)d_in[14];
    float* out = (float*)d_out;

    k_init<<<128,256>>>(sent);
    // encoder input proj: M=4096, N=2048, K=256
    k_gemm<0><<<dim3(16,32,1),256>>>(emb, eWih, eWih, eB, eB, 0, 1<<30, 0);
    // decoder input proj: M=4352 (2x2176), dir split at 2176
    k_gemm<0><<<dim3(16,34,1),256>>>(emb, fWih, bWih, fB, bB, 1, PDROWS, 0);
    // persistent encoder
    k_enc<<<128,256>>>(eWhh);
    k_decinit<<<8192,256>>>();
    for (int s=0; s<4; s++){
        k_gemm<1><<<dim3(16,32,1),256>>>(emb, fWhh, bWhh, 0, 0, 0, 2048, s);
        k_cell<<<4096,512>>>(s);
    }
    k_picks<<<3072,256>>>(fhW, bhW, fhb, bhb);
    // vocab logits + fused partial LSE: z-dim = 4 decoder steps
    k_gemm<2><<<dim3(63,32,4),256>>>(emb, fhW, bhW, fhb, bhb, 0, 2048, 0);
    k_lse2<<<64,256>>>();
    k_res<<<16,256>>>();
    k_final<<<1,32>>>(out);
}

// round 3
// speedup vs baseline: 4.4079x; 1.6677x over previous
#include <cuda_runtime.h>
#include <cuda_bf16.h>
#include <math.h>

#define BB 32
#define TT 64
#define VV 8000
#define EE 256
#define HH 512
#define GG 2048
#define WW 3
#define NEGF (-1e30f)
#define NDROW 4096
#define ROWS_E 64
#define PDT 68
#define PDROWS (PDT*BB)      // 2176
#define NP 250
#define SR (4*NDROW)

typedef __nv_bfloat16 bf16;

// ----- fp32 scratch -----
__device__ float d_Xe[TT*ROWS_E*GG];
__device__ float d_Henc[2*(TT+1)*BB*HH];
__device__ float d_Pd[2*PDROWS*GG];
__device__ float d_G[NDROW*GG];
__device__ float d_Hdec[5*NDROW*HH];
__device__ float d_Cdec[2*NDROW*HH];
__device__ int   d_tokE[TT*ROWS_E];
__device__ int   d_tokD[2*PDROWS];
__device__ float d_zc[3*NDROW];
__device__ float d_zt[4*NDROW];
__device__ float d_part[NP*SR*2];
__device__ float d_lse[4*NDROW];
__device__ float d_res[2*TT*WW*BB];
__device__ unsigned g_cnt;
__device__ unsigned g_gen;

// ----- bf16 mirrors -----
__device__ bf16 d_embB[VV*EE];
__device__ bf16 d_WeIB[GG*EE];
__device__ bf16 d_WfIB[GG*EE];
__device__ bf16 d_WbIB[GG*EE];
__device__ bf16 d_WfHB[GG*HH];
__device__ bf16 d_WbHB[GG*HH];
__device__ bf16 d_hWfB[VV*HH];
__device__ bf16 d_hWbB[VV*HH];
__device__ bf16 d_HencB[2*(TT+1)*BB*HH];
__device__ bf16 d_HdecB[5*NDROW*HH];

__device__ __forceinline__ float sigm(float x){ return 1.f/(1.f+__expf(-x)); }
__device__ __forceinline__ unsigned sptr(const void* p){
    return (unsigned)__cvta_generic_to_shared(p);
}
__device__ __forceinline__ void ldsm4(unsigned* r, unsigned a){
    asm volatile("ldmatrix.sync.aligned.m8n8.x4.shared.b16 {%0,%1,%2,%3}, [%4];\n"
        : "=r"(r[0]),"=r"(r[1]),"=r"(r[2]),"=r"(r[3]) : "r"(a));
}
__device__ __forceinline__ void mma16(float* c, const unsigned* a, const unsigned* b){
    asm volatile("mma.sync.aligned.m16n8k16.row.col.f32.bf16.bf16.f32 "
        "{%0,%1,%2,%3},{%4,%5,%6,%7},{%8,%9},{%0,%1,%2,%3};\n"
        : "+f"(c[0]),"+f"(c[1]),"+f"(c[2]),"+f"(c[3])
        : "r"(a[0]),"r"(a[1]),"r"(a[2]),"r"(a[3]),"r"(b[0]),"r"(b[1]));
}

// ----- fp32 -> bf16 conversion -----
__global__ void k_conv(bf16* __restrict__ dst, const float* __restrict__ src, int n){
    int i = (blockIdx.x*blockDim.x + threadIdx.x)*4;
    if (i < n){
        float4 v = *(const float4*)(src+i);
        *(__nv_bfloat162*)(dst+i)   = __floats2bfloat162_rn(v.x, v.y);
        *(__nv_bfloat162*)(dst+i+2) = __floats2bfloat162_rn(v.z, v.w);
    }
}

// ----- init -----
__global__ void k_init(const int* __restrict__ sent){
    int i = blockIdx.x*blockDim.x + threadIdx.x;   // 32768 threads
    if (i == 0){ g_cnt = 0u; g_gen = 0u; }
    if (i < 2*BB*HH){
        int dir = i/(BB*HH); int rem = i%(BB*HH);
        d_HencB[(dir*(TT+1))*BB*HH + rem] = __float2bfloat16(0.f);
    }
    if (i < TT*ROWS_E){
        int t = i/ROWS_E, r = i%ROWS_E, dir = r/BB, b = r%BB;
        int tok = (t==0) ? 0 : (dir ? sent[b*TT + (TT-t)] : sent[b*TT + (t-1)]);
        d_tokE[i] = tok;
    }
    if (i < 2*PDROWS){
        int dir = i/PDROWS; int rem = i%PDROWS; int t = rem/BB, b = rem%BB;
        int tok = (t < TT) ? (dir ? sent[b*TT + (TT-1-t)] : sent[b*TT + t]) : 0;
        d_tokD[i] = tok;
    }
}

// ===================== bf16 mma GEMM, 128x128 tile =====================
// MODE 0: A = embB[tok[m]], K=256, out = Xe/Pd (+bias)
// MODE 1: A = HdecB[s],  K=512, out = d_G (+Pd x-row)
// MODE 2: A = HdecB[s+1],K=512, fused partial LSE over 32-wide vocab strips
template<int MODE>
__global__ void __launch_bounds__(256) k_bgemm(
    const float* __restrict__ bias0, const float* __restrict__ bias1,
    int gsel, int mhalf, int s)
{
    constexpr int KD = (MODE==0)? EE : HH;
    constexpr int NC = KD/32;
    __shared__ bf16 sA[2][128*40];
    __shared__ bf16 sB[2][128*40];
    const int tid = threadIdx.x;
    const int m0 = blockIdx.y*128, n0 = blockIdx.x*128;
    const int ss = (MODE==2)? (int)blockIdx.z : s;
    const int dir = (m0 >= mhalf)? 1 : 0;
    const bf16* Bm;
    if (MODE==0) Bm = gsel? (dir? d_WbIB : d_WfIB) : d_WeIB;
    else if (MODE==1) Bm = dir? d_WbHB : d_WfHB;
    else Bm = dir? d_hWbB : d_hWfB;
    const float* bias = dir? bias1 : bias0;

    const int lrow = tid>>1, lo = (tid&1)*16;
    const bf16* arow;
    if (MODE==0){
        const int* tok = gsel? d_tokD : d_tokE;
        arow = d_embB + (long)tok[m0+lrow]*KD;
    } else if (MODE==1){
        arow = d_HdecB + (long)ss*NDROW*HH + (long)(m0+lrow)*HH;
    } else {
        arow = d_HdecB + (long)(ss+1)*NDROW*HH + (long)(m0+lrow)*HH;
    }
    const int vrow = n0 + lrow;
    const bool bval = (MODE!=2) || (vrow < VV);
    const bf16* brow = Bm + (long)(bval? vrow : 0)*KD;

    uint4 pa0 = *(const uint4*)(arow+lo), pa1 = *(const uint4*)(arow+lo+8);
    uint4 pb0 = *(const uint4*)(brow+lo), pb1 = *(const uint4*)(brow+lo+8);
    *(uint4*)&sA[0][lrow*40+lo] = pa0; *(uint4*)&sA[0][lrow*40+lo+8] = pa1;
    *(uint4*)&sB[0][lrow*40+lo] = pb0; *(uint4*)&sB[0][lrow*40+lo+8] = pb1;
    __syncthreads();

    const int lane = tid&31, warp = tid>>5;
    const int wm = warp&1, wn = warp>>1;
    const int g = lane>>2, t4 = lane&3;
    const int rl = (lane&7) + ((lane>>3)&1)*8;
    const int ca = (lane>>4)*8;
    const int rb = (lane&7) + ((lane>>4)&1)*8;
    const int cb = ((lane>>3)&1)*8;

    float acc[4][4][4];
    #pragma unroll
    for (int i=0;i<4;i++)
        #pragma unroll
        for (int j=0;j<4;j++)
            #pragma unroll
            for (int e=0;e<4;e++) acc[i][j][e]=0.f;

    #pragma unroll 1
    for (int kt=0; kt<NC; kt++){
        if (kt+1 < NC){
            int kc = (kt+1)*32;
            pa0 = *(const uint4*)(arow+kc+lo); pa1 = *(const uint4*)(arow+kc+lo+8);
            pb0 = *(const uint4*)(brow+kc+lo); pb1 = *(const uint4*)(brow+kc+lo+8);
        }
        const bf16* Ab = sA[kt&1];
        const bf16* Bb = sB[kt&1];
        #pragma unroll
        for (int ks=0; ks<32; ks+=16){
            unsigned af[4][4], bfm[2][4];
            #pragma unroll
            for (int mf=0;mf<4;mf++)
                ldsm4(af[mf], sptr(Ab + (wm*64+mf*16+rl)*40 + ks + ca));
            #pragma unroll
            for (int p=0;p<2;p++)
                ldsm4(bfm[p], sptr(Bb + (wn*32+p*16+rb)*40 + ks + cb));
            #pragma unroll
            for (int mf=0;mf<4;mf++)
                #pragma unroll
                for (int nf=0;nf<4;nf++)
                    mma16(acc[mf][nf], af[mf], &bfm[nf>>1][(nf&1)*2]);
        }
        __syncthreads();
        if (kt+1 < NC){
            int nb = (kt+1)&1;
            *(uint4*)&sA[nb][lrow*40+lo] = pa0; *(uint4*)&sA[nb][lrow*40+lo+8] = pa1;
            *(uint4*)&sB[nb][lrow*40+lo] = pb0; *(uint4*)&sB[nb][lrow*40+lo+8] = pb1;
            __syncthreads();
        }
    }

    if (MODE==0){
        float* Co = gsel? d_Pd : d_Xe;
        #pragma unroll
        for (int mf=0; mf<4; mf++)
            #pragma unroll
            for (int lohi=0; lohi<2; lohi++){
                int r = m0 + wm*64 + mf*16 + g + lohi*8;
                #pragma unroll
                for (int nf=0; nf<4; nf++){
                    int col = n0 + wn*32 + nf*8 + 2*t4;
                    float2 o;
                    o.x = acc[mf][nf][lohi*2+0] + bias[col];
                    o.y = acc[mf][nf][lohi*2+1] + bias[col+1];
                    *(float2*)&Co[(long)r*GG + col] = o;
                }
            }
    } else if (MODE==1){
        #pragma unroll
        for (int mf=0; mf<4; mf++)
            #pragma unroll
            for (int lohi=0; lohi<2; lohi++){
                int r = m0 + wm*64 + mf*16 + g + lohi*8;
                int rr = r - dir*2048;
                int m = rr>>5, b2 = rr&31;
                int tp = (ss==0)? TT : min(m+ss-1, TT-1);
                const float* xr = d_Pd + ((long)(dir*PDT+tp)*BB + b2)*GG;
                #pragma unroll
                for (int nf=0; nf<4; nf++){
                    int col = n0 + wn*32 + nf*8 + 2*t4;
                    float2 o;
                    o.x = acc[mf][nf][lohi*2+0] + xr[col];
                    o.y = acc[mf][nf][lohi*2+1] + xr[col+1];
                    *(float2*)&d_G[(long)r*GG + col] = o;
                }
            }
    } else {
        int nb = (n0>>5) + wn;
        #pragma unroll
        for (int mf=0; mf<4; mf++)
            #pragma unroll
            for (int lohi=0; lohi<2; lohi++){
                int r = m0 + wm*64 + mf*16 + g + lohi*8;
                float z[8]; float mx = NEGF;
                #pragma unroll
                for (int nf=0; nf<4; nf++)
                    #pragma unroll
                    for (int e=0; e<2; e++){
                        int v = n0 + wn*32 + nf*8 + 2*t4 + e;
                        float zz = acc[mf][nf][lohi*2+e] + ((v<VV)? bias[v] : NEGF);
                        z[nf*2+e] = zz;
                        mx = fmaxf(mx, zz);
                    }
                mx = fmaxf(mx, __shfl_xor_sync(0xffffffffu, mx, 1));
                mx = fmaxf(mx, __shfl_xor_sync(0xffffffffu, mx, 2));
                float sm = 0.f;
                #pragma unroll
                for (int j=0;j<8;j++) sm += __expf(z[j]-mx);
                sm += __shfl_xor_sync(0xffffffffu, sm, 1);
                sm += __shfl_xor_sync(0xffffffffu, sm, 2);
                if (t4==0 && nb < NP){
                    int srow = ss*NDROW + r;
                    d_part[((long)nb*SR + srow)*2    ] = mx;
                    d_part[((long)nb*SR + srow)*2 + 1] = sm;
                }
            }
    }
}

// ===================== tensor-core persistent encoder =====================
// 32 blocks; block owns 16 h-columns (64 gate-cols, gate-interleaved: c=4q+g).
// Whh slice bf16 in smem (once). Per step: stage H bf16, mma, cell, grid barrier.
#define ESM_BYTES (64*520*2 + 2*64*136*2 + 64*66*4)
__global__ void __launch_bounds__(256) k_enc(const float* __restrict__ Whh){
    extern __shared__ char esm[];
    bf16* Ws  = (bf16*)esm;                       // [64 c][520]
    bf16* As  = Ws + 64*520;                      // [2][64][136]
    float* Gs = (float*)(As + 2*64*136);          // [64][66]
    const int tid = threadIdx.x;
    const int h0 = blockIdx.x*16;

    {   // load + convert Whh slice, permuted: col c=4q+g <- Whh row g*512+h0+q
        int c = tid>>2, t4w = tid&3;
        int gg = c&3, q = c>>2;
        const float* wr = Whh + (long)(gg*HH + h0 + q)*HH + t4w*128;
        bf16* dst = Ws + c*520 + t4w*128;
        #pragma unroll 4
        for (int j=0;j<128;j+=4){
            float4 v = *(const float4*)(wr+j);
            dst[j]   = __float2bfloat16_rn(v.x);
            dst[j+1] = __float2bfloat16_rn(v.y);
            dst[j+2] = __float2bfloat16_rn(v.z);
            dst[j+3] = __float2bfloat16_rn(v.w);
        }
    }
    __syncthreads();

    const int lane = tid&31, warp = tid>>5;
    const int wr4 = warp&3, wc = warp>>2;
    const int g = lane>>2, t4 = lane&3;
    const int rl = (lane&7) + ((lane>>3)&1)*8;
    const int ca = (lane>>4)*8;
    const int rb = (lane&7) + ((lane>>4)&1)*8;
    const int cb = ((lane>>3)&1)*8;
    const int srow = tid>>2, soff = (tid&3)*32;
    const int sdir = srow>>5, sb = srow&31;
    const int r = tid>>2, l4 = tid&3;
    const int dir = r>>5, b = r&31;

    float cst[4] = {0.f,0.f,0.f,0.f};
    unsigned gen = 0;

    for (int t=0; t<TT; t++){
        const bf16* hbase = d_HencB + ((long)(sdir*(TT+1)+t)*BB + sb)*HH + soff;
        // chunk 0
        {
            uint4 v0 = *(const uint4*)(hbase);
            uint4 v1 = *(const uint4*)(hbase+8);
            uint4 v2 = *(const uint4*)(hbase+16);
            uint4 v3 = *(const uint4*)(hbase+24);
            bf16* dst = As + srow*136 + soff;
            *(uint4*)dst = v0; *(uint4*)(dst+8) = v1;
            *(uint4*)(dst+16) = v2; *(uint4*)(dst+24) = v3;
        }
        __syncthreads();

        float acc[4][4];
        #pragma unroll
        for (int nf=0;nf<4;nf++)
            #pragma unroll
            for (int e=0;e<4;e++) acc[nf][e]=0.f;

        #pragma unroll 1
        for (int c4=0; c4<4; c4++){
            uint4 v0,v1,v2,v3;
            if (c4+1 < 4){
                const bf16* src = hbase + (c4+1)*128;
                v0 = *(const uint4*)(src); v1 = *(const uint4*)(src+8);
                v2 = *(const uint4*)(src+16); v3 = *(const uint4*)(src+24);
            }
            const bf16* Ab = As + (c4&1)*64*136;
            const int kc = c4*128;
            #pragma unroll
            for (int ks=0; ks<128; ks+=16){
                unsigned af[4], bfm[2][4];
                ldsm4(af, sptr(Ab + (16*wr4+rl)*136 + ks + ca));
                #pragma unroll
                for (int p=0;p<2;p++)
                    ldsm4(bfm[p], sptr(Ws + (wc*32+p*16+rb)*520 + kc + ks + cb));
                #pragma unroll
                for (int nf=0;nf<4;nf++)
                    mma16(acc[nf], af, &bfm[nf>>1][(nf&1)*2]);
            }
            __syncthreads();
            if (c4+1 < 4){
                bf16* dst = As + ((c4+1)&1)*64*136 + srow*136 + soff;
                *(uint4*)dst = v0; *(uint4*)(dst+8) = v1;
                *(uint4*)(dst+16) = v2; *(uint4*)(dst+24) = v3;
                __syncthreads();
            }
        }
        // stage gates
        #pragma unroll
        for (int nf=0;nf<4;nf++){
            int col = wc*32 + nf*8 + 2*t4;
            Gs[(16*wr4+g)*66 + col]   = acc[nf][0];
            Gs[(16*wr4+g)*66 + col+1] = acc[nf][1];
            Gs[(16*wr4+g+8)*66 + col]   = acc[nf][2];
            Gs[(16*wr4+g+8)*66 + col+1] = acc[nf][3];
        }
        __syncthreads();
        // cell update: thread handles (r, h0 + l4 + 4j), j=0..3
        {
            const float* xb = d_Xe + (long)(t*ROWS_E + r)*GG;
            #pragma unroll
            for (int j=0;j<4;j++){
                int q = l4 + 4*j; int h = h0 + q;
                float gi = Gs[r*66 + 4*q + 0] + xb[h];
                float gf = Gs[r*66 + 4*q + 1] + xb[HH+h];
                float g2 = Gs[r*66 + 4*q + 2] + xb[2*HH+h];
                float go = Gs[r*66 + 4*q + 3] + xb[3*HH+h];
                cst[j] = sigm(gf)*cst[j] + sigm(gi)*tanhf(g2);
                float hn = sigm(go)*tanhf(cst[j]);
                long oi = ((long)(dir*(TT+1)+(t+1))*BB + b)*HH + h;
                d_Henc[oi]  = hn;
                d_HencB[oi] = __float2bfloat16_rn(hn);
            }
        }
        // grid barrier
        __threadfence();
        __syncthreads();
        if (tid==0){
            unsigned a = atomicAdd(&g_cnt, 1u);
            if (a == gridDim.x-1){
                g_cnt = 0;
                __threadfence();
                atomicExch(&g_gen, gen+1u);
            } else {
                while (*((volatile unsigned*)&g_gen) != gen+1u) __nanosleep(32);
                __threadfence();
            }
        }
        __syncthreads();
        gen++;
    }
}

// ----- decoder init -----
__global__ void k_decinit(){
    int i = blockIdx.x*blockDim.x + threadIdx.x;
    int row = i>>9, h = i&511;
    int dir = row>>11, rr = row&2047, m = rr>>5, b = rr&31;
    float v = d_Henc[((long)(dir*(TT+1)+(m+1))*BB+b)*HH + h];
    d_Hdec[i] = v;
    d_Cdec[i] = v;
    d_HdecB[i] = __float2bfloat16_rn(v);
}

// ----- decoder cell -----
__global__ void k_cell(int s){
    int i = blockIdx.x*blockDim.x + threadIdx.x;
    int row = i>>9, h = i&511;
    const float* gr = d_G + (long)row*GG;
    float gi = gr[h], gf = gr[HH+h], g2 = gr[2*HH+h], go = gr[3*HH+h];
    float cp = d_Cdec[(s&1)*NDROW*HH + i];
    float c = sigm(gf)*cp + sigm(gi)*tanhf(g2);
    float hn = sigm(go)*tanhf(c);
    d_Cdec[((s+1)&1)*NDROW*HH + i] = c;
    d_Hdec[(s+1)*NDROW*HH + i] = hn;
    d_HdecB[(long)(s+1)*NDROW*HH + i] = __float2bfloat16_rn(hn);
}

// ----- gathered picks -----
__global__ void k_picks(const float* __restrict__ fhW, const float* __restrict__ bhW,
                        const float* __restrict__ fhb, const float* __restrict__ bhb){
    int w = (blockIdx.x*blockDim.x + threadIdx.x) >> 5;
    int lane = threadIdx.x & 31;
    if (w >= 6*NDROW) return;
    int kind = w / NDROW;
    int row  = w % NDROW;
    int dir = row>>11, rr = row&2047, m = rr>>5, b = rr&31;
    const float* hW = dir ? bhW : fhW;
    const float* hb = dir ? bhb : fhb;
    int s, y;
    if (kind < 3){ s = kind;   y = d_tokD[dir*PDROWS + min(m+s, TT-1)*BB + b]; }
    else         { s = kind-2; y = 0; }
    const float* h = d_Hdec + (long)(s+1)*NDROW*HH + (long)row*HH;
    const float* wv = hW + (long)y*HH;
    float sum = 0.f;
    #pragma unroll 4
    for (int k=lane; k<HH; k+=32) sum += h[k]*wv[k];
    #pragma unroll
    for (int off=16; off; off>>=1) sum += __shfl_xor_sync(0xffffffffu, sum, off);
    if (!lane){
        if (kind < 3) d_zc[s*NDROW + row] = sum + hb[y];
        else          d_zt[s*NDROW + row] = sum + hb[0];
    }
}

// ----- combine LSE partials -----
__global__ void k_lse2(){
    int i = blockIdx.x*blockDim.x + threadIdx.x;
    if (i >= SR) return;
    float mx = NEGF, sm = 0.f;
    for (int nb=0; nb<NP; nb++){
        float2 p = *(float2*)&d_part[((long)nb*SR + i)*2];
        if (p.x > mx){ sm = sm*__expf(mx-p.x) + p.y; mx = p.x; }
        else sm += p.y*__expf(p.x-mx);
    }
    d_lse[i] = mx + logf(sm);
}

// ----- segment scores -----
__global__ void k_res(){
    int i = blockIdx.x*blockDim.x + threadIdx.x;
    if (i >= NDROW) return;
    int dir = i>>11, rr = i&2047, m = rr>>5, b = rr&31;
    float cum = 0.f;
    #pragma unroll
    for (int l=0; l<WW; l++){
        cum += d_zc[l*NDROW+i] - d_lse[l*NDROW+i];
        float tg = d_zt[(l+1)*NDROW+i] - d_lse[(l+1)*NDROW+i];
        d_res[((dir*TT+m)*WW+l)*BB + b] = cum + tg;
    }
}

// ----- final DP -----
__global__ void k_final(float* __restrict__ out){
    int b = threadIdx.x;
    float w0 = 0.f, w1 = NEGF, w2 = NEGF;
    for (int e=0; e<TT; e++){
        float p[3];
        #pragma unroll
        for (int l=0; l<3; l++){
            int st = e - l;
            p[l] = (st >= 0) ? (d_res[((0*TT+st)*WW+l)*BB + b]
                              + d_res[((1*TT+(TT-1-e))*WW+l)*BB + b]) : NEGF;
        }
        float x0 = w0+p[0], x1 = w1+p[1], x2 = w2+p[2];
        float m = fmaxf(x0, fmaxf(x1, x2));
        float tot = m + logf(__expf(x0-m) + __expf(x1-m) + __expf(x2-m));
        w2 = w1; w1 = w0; w0 = tot;
    }
    float v = w0;
    #pragma unroll
    for (int off=16; off; off>>=1) v += __shfl_xor_sync(0xffffffffu, v, off);
    if (b == 0) out[0] = -v/(float)BB;
}

extern "C" void kernel_launch(void* const* d_in, const int* in_sizes, int n_in,
                              void* d_out, int out_size){
    const int*   sent = (const int*)  d_in[0];
    const float* emb  = (const float*)d_in[1];
    const float* eWih = (const float*)d_in[2];
    const float* eWhh = (const float*)d_in[3];
    const float* eB   = (const float*)d_in[4];
    const float* fWih = (const float*)d_in[5];
    const float* fWhh = (const float*)d_in[6];
    const float* fB   = (const float*)d_in[7];
    const float* fhW  = (const float*)d_in[8];
    const float* fhb  = (const float*)d_in[9];
    const float* bWih = (const float*)d_in[10];
    const float* bWhh = (const float*)d_in[11];
    const float* bB   = (const float*)d_in[12];
    const float* bhW  = (const float*)d_in[13];
    const float* bhb  = (const float*)d_in[14];
    float* out = (float*)d_out;

    cudaFuncSetAttribute(k_enc, cudaFuncAttributeMaxDynamicSharedMemorySize, ESM_BYTES);

    k_init<<<128,256>>>(sent);
    // bf16 weight/embedding mirrors
    bf16* dsts[8];  const float* srcs[8]; int ns[8];
    { // resolve device-global addresses via symbols is implicit: use direct refs in kernels;
      // here we launch k_conv with device pointers obtained from cudaGetSymbolAddress-free
      // trick: small launcher kernels would cost more; instead pass via template-free calls:
    }
    {
        void* p;
        cudaGetSymbolAddress(&p, d_embB); k_conv<<<(VV*EE/4+255)/256,256>>>((bf16*)p, emb, VV*EE);
        cudaGetSymbolAddress(&p, d_WeIB); k_conv<<<(GG*EE/4+255)/256,256>>>((bf16*)p, eWih, GG*EE);
        cudaGetSymbolAddress(&p, d_WfIB); k_conv<<<(GG*EE/4+255)/256,256>>>((bf16*)p, fWih, GG*EE);
        cudaGetSymbolAddress(&p, d_WbIB); k_conv<<<(GG*EE/4+255)/256,256>>>((bf16*)p, bWih, GG*EE);
        cudaGetSymbolAddress(&p, d_WfHB); k_conv<<<(GG*HH/4+255)/256,256>>>((bf16*)p, fWhh, GG*HH);
        cudaGetSymbolAddress(&p, d_WbHB); k_conv<<<(GG*HH/4+255)/256,256>>>((bf16*)p, bWhh, GG*HH);
        cudaGetSymbolAddress(&p, d_hWfB); k_conv<<<(VV*HH/4+255)/256,256>>>((bf16*)p, fhW, VV*HH);
        cudaGetSymbolAddress(&p, d_hWbB); k_conv<<<(VV*HH/4+255)/256,256>>>((bf16*)p, bhW, VV*HH);
    }
    // encoder input proj: M=4096, N=2048, K=256
    k_bgemm<0><<<dim3(16,32,1),256>>>(eB, eB, 0, 1<<30, 0);
    // decoder input proj: M=4352, dir split at 2176
    k_bgemm<0><<<dim3(16,34,1),256>>>(fB, bB, 1, PDROWS, 0);
    // persistent tensor-core encoder
    k_enc<<<32,256,ESM_BYTES>>>(eWhh);
    k_decinit<<<8192,256>>>();
    for (int s=0; s<4; s++){
        k_bgemm<1><<<dim3(16,32,1),256>>>(0, 0, 0, 2048, s);
        k_cell<<<4096,512>>>(s);
    }
    k_picks<<<3072,256>>>(fhW, bhW, fhb, bhb);
    k_bgemm<2><<<dim3(63,32,4),256>>>(fhb, bhb, 0, 2048, 0);
    k_lse2<<<64,256>>>();
    k_res<<<16,256>>>();
    k_final<<<1,32>>>(out);
}

// round 7
// speedup vs baseline: 4.6593x; 1.0570x over previous
#include <cuda_runtime.h>
#include <cuda_bf16.h>
#include <stdint.h>
#include <math.h>

#define BB 32
#define TT 64
#define VV 8000
#define EE 256
#define HH 512
#define GG 2048
#define WW 3
#define NEGF (-1e30f)
#define NDROW 4096
#define ROWS_E 64
#define PDT 68
#define PDROWS (PDT*BB)      // 2176
#define NP 250               // vocab partial strips of 32
#define SR (4*NDROW)

typedef __nv_bfloat16 bf16;

// ----- fp32 scratch -----
__device__ float d_Xe[TT*ROWS_E*GG];
__device__ float d_Henc[2*(TT+1)*BB*HH];
__device__ float d_Pd[2*PDROWS*GG];
__device__ float d_G[NDROW*GG];
__device__ float d_Hdec[5*NDROW*HH];
__device__ float d_Cdec[2*NDROW*HH];
__device__ int   d_tokE[TT*ROWS_E];
__device__ int   d_tokD[2*PDROWS];
__device__ float d_zc[3*NDROW];
__device__ float d_zt[4*NDROW];
__device__ float d_part[NP*SR*2];
__device__ float d_lse[4*NDROW];
__device__ float d_res[2*TT*WW*BB];
__device__ unsigned g_cnt;
__device__ unsigned g_gen;

// ----- bf16 mirrors -----
__device__ bf16 d_embB[VV*EE];
__device__ bf16 d_WeIB[GG*EE];
__device__ bf16 d_WfIB[GG*EE];
__device__ bf16 d_WbIB[GG*EE];
__device__ bf16 d_WfHB[GG*HH];
__device__ bf16 d_WbHB[GG*HH];
__device__ bf16 d_hWfB[VV*HH];
__device__ bf16 d_hWbB[VV*HH];
__device__ bf16 d_HencB[2*(TT+1)*BB*HH];
__device__ bf16 d_HdecB[5*NDROW*HH];

__device__ __forceinline__ float sigm(float x){ return 1.f/(1.f+__expf(-x)); }
__device__ __forceinline__ unsigned sptr(const void* p){
    return (unsigned)__cvta_generic_to_shared(p);
}
__device__ __forceinline__ void ldsm4(unsigned* r, unsigned a){
    asm volatile("ldmatrix.sync.aligned.m8n8.x4.shared.b16 {%0,%1,%2,%3}, [%4];\n"
        : "=r"(r[0]),"=r"(r[1]),"=r"(r[2]),"=r"(r[3]) : "r"(a));
}
__device__ __forceinline__ void mma16(float* c, const unsigned* a, const unsigned* b){
    asm volatile("mma.sync.aligned.m16n8k16.row.col.f32.bf16.bf16.f32 "
        "{%0,%1,%2,%3},{%4,%5,%6,%7},{%8,%9},{%0,%1,%2,%3};\n"
        : "+f"(c[0]),"+f"(c[1]),"+f"(c[2]),"+f"(c[3])
        : "r"(a[0]),"r"(a[1]),"r"(a[2]),"r"(a[3]),"r"(b[0]),"r"(b[1]));
}
__device__ __forceinline__ void cp16(unsigned dst, const void* src, int ssz){
    asm volatile("cp.async.cg.shared.global [%0], [%1], 16, %2;\n"
        :: "r"(dst), "l"(src), "r"(ssz));
}

// ----- fp32 -> bf16 conversion (2 merged kernels) -----
__global__ void k_convA(const float* __restrict__ emb, const float* __restrict__ eWih,
                        const float* __restrict__ fWih, const float* __restrict__ bWih){
    const long n0 = (long)VV*EE, n1 = n0 + (long)GG*EE, n2 = n1 + (long)GG*EE, n3 = n2 + (long)GG*EE;
    long i = ((long)blockIdx.x*blockDim.x + threadIdx.x)*4;
    if (i >= n3) return;
    const float* src; bf16* dst; long off;
    if (i < n0){ src=emb; dst=d_embB; off=i; }
    else if (i < n1){ src=eWih; dst=d_WeIB; off=i-n0; }
    else if (i < n2){ src=fWih; dst=d_WfIB; off=i-n1; }
    else { src=bWih; dst=d_WbIB; off=i-n2; }
    float4 v = *(const float4*)(src+off);
    *(__nv_bfloat162*)(dst+off)   = __floats2bfloat162_rn(v.x, v.y);
    *(__nv_bfloat162*)(dst+off+2) = __floats2bfloat162_rn(v.z, v.w);
}
__global__ void k_convB(const float* __restrict__ fWhh, const float* __restrict__ bWhh,
                        const float* __restrict__ fhW, const float* __restrict__ bhW){
    const long n0 = (long)GG*HH, n1 = n0 + (long)GG*HH, n2 = n1 + (long)VV*HH, n3 = n2 + (long)VV*HH;
    long i = ((long)blockIdx.x*blockDim.x + threadIdx.x)*4;
    if (i >= n3) return;
    const float* src; bf16* dst; long off;
    if (i < n0){ src=fWhh; dst=d_WfHB; off=i; }
    else if (i < n1){ src=bWhh; dst=d_WbHB; off=i-n0; }
    else if (i < n2){ src=fhW; dst=d_hWfB; off=i-n1; }
    else { src=bhW; dst=d_hWbB; off=i-n2; }
    float4 v = *(const float4*)(src+off);
    *(__nv_bfloat162*)(dst+off)   = __floats2bfloat162_rn(v.x, v.y);
    *(__nv_bfloat162*)(dst+off+2) = __floats2bfloat162_rn(v.z, v.w);
}

// ----- init -----
__global__ void k_init(const int* __restrict__ sent){
    int i = blockIdx.x*blockDim.x + threadIdx.x;
    if (i == 0){ g_cnt = 0u; g_gen = 0u; }
    if (i < 2*BB*HH){
        int dir = i/(BB*HH); int rem = i%(BB*HH);
        d_HencB[(dir*(TT+1))*BB*HH + rem] = __float2bfloat16(0.f);
    }
    if (i < TT*ROWS_E){
        int t = i/ROWS_E, r = i%ROWS_E, dir = r/BB, b = r%BB;
        int tok = (t==0) ? 0 : (dir ? sent[b*TT + (TT-t)] : sent[b*TT + (t-1)]);
        d_tokE[i] = tok;
    }
    if (i < 2*PDROWS){
        int dir = i/PDROWS; int rem = i%PDROWS; int t = rem/BB, b = rem%BB;
        int tok = (t < TT) ? (dir ? sent[b*TT + (TT-1-t)] : sent[b*TT + t]) : 0;
        d_tokD[i] = tok;
    }
}

// ===================== bf16 mma.sync GEMM, cp.async 3-stage pipeline =====================
#define BG_SMEM (2*3*128*40*2)     // 61440 bytes
extern __shared__ bf16 dynsm[];

template<int MODE>
__global__ void __launch_bounds__(256) k_bgemm(
    const float* __restrict__ bias0, const float* __restrict__ bias1,
    int gsel, int mhalf, int s)
{
    constexpr int KD = (MODE==0)? EE : HH;
    constexpr int NC = KD/32;
    bf16* sA = dynsm;                 // [3][128*40]
    bf16* sB = dynsm + 3*5120;        // [3][128*40]
    const int tid = threadIdx.x;
    const int m0 = blockIdx.y*128, n0 = blockIdx.x*128;
    const int ss = (MODE==2)? (int)blockIdx.z : s;     // <-- restored MODE2 step select
    const int dir = (m0 >= mhalf)? 1 : 0;
    const bf16* Bm;
    if (MODE==0) Bm = gsel? (dir? d_WbIB : d_WfIB) : d_WeIB;
    else if (MODE==1) Bm = dir? d_WbHB : d_WfHB;
    else Bm = dir? d_hWbB : d_hWfB;
    const float* bias = dir? bias1 : bias0;

    const int lrow = tid>>1, lc = (tid&1)*16;
    const bf16* arow;
    if (MODE==0){
        const int* tok = gsel? d_tokD : d_tokE;
        arow = d_embB + (long)tok[m0+lrow]*KD;
    } else if (MODE==1){
        arow = d_HdecB + (long)ss*NDROW*HH + (long)(m0+lrow)*HH;
    } else {
        arow = d_HdecB + (long)(ss+1)*NDROW*HH + (long)(m0+lrow)*HH;
    }
    const int vrow = n0 + lrow;
    const bool bval = (MODE!=2) || (vrow < VV);
    const bf16* brow = Bm + (long)(bval? vrow : 0)*KD;
    const int bok = bval? 16 : 0;

    const unsigned smA = sptr(sA), smB = sptr(sB);
    const unsigned ldoff = (unsigned)(lrow*80 + (tid&1)*32);

    auto issue_chunk = [&](int kt, int st){
        int k0 = kt*32;
        unsigned adst = smA + (unsigned)st*10240u + ldoff;
        cp16(adst,      arow + k0 + lc,     16);
        cp16(adst+16u,  arow + k0 + lc + 8, 16);
        unsigned bdst = smB + (unsigned)st*10240u + ldoff;
        cp16(bdst,      brow + k0 + lc,     bok);
        cp16(bdst+16u,  brow + k0 + lc + 8, bok);
        asm volatile("cp.async.commit_group;" ::: "memory");
    };

    const int lane = tid&31, warp = tid>>5;
    const int wm = warp&1, wn = warp>>1;
    const int g = lane>>2, t4 = lane&3;
    const int rl = (lane&7) + ((lane>>3)&1)*8;
    const int ca = (lane>>4)*8;
    const int rb = (lane&7) + ((lane>>4)&1)*8;
    const int cb = ((lane>>3)&1)*8;

    float acc[4][4][4];
    #pragma unroll
    for (int i=0;i<4;i++)
        #pragma unroll
        for (int j=0;j<4;j++)
            #pragma unroll
            for (int e=0;e<4;e++) acc[i][j][e]=0.f;

    issue_chunk(0, 0);
    issue_chunk(1, 1);

    #pragma unroll 1
    for (int kt=0; kt<NC; kt++){
        asm volatile("cp.async.wait_group 1;" ::: "memory");
        __syncthreads();
        int nx = kt + 2;
        if (nx < NC) issue_chunk(nx, nx%3);
        else asm volatile("cp.async.commit_group;" ::: "memory");
        const bf16* Ab = sA + (kt%3)*5120;
        const bf16* Bb = sB + (kt%3)*5120;
        #pragma unroll
        for (int ks=0; ks<32; ks+=16){
            unsigned af[4][4], bfm[2][4];
            #pragma unroll
            for (int mf=0;mf<4;mf++)
                ldsm4(af[mf], sptr(Ab + (wm*64+mf*16+rl)*40 + ks + ca));
            #pragma unroll
            for (int p=0;p<2;p++)
                ldsm4(bfm[p], sptr(Bb + (wn*32+p*16+rb)*40 + ks + cb));
            #pragma unroll
            for (int mf=0;mf<4;mf++)
                #pragma unroll
                for (int nf=0;nf<4;nf++)
                    mma16(acc[mf][nf], af[mf], &bfm[nf>>1][(nf&1)*2]);
        }
    }

    if (MODE==0){
        float* Co = gsel? d_Pd : d_Xe;
        #pragma unroll
        for (int mf=0; mf<4; mf++)
            #pragma unroll
            for (int lohi=0; lohi<2; lohi++){
                int r = m0 + wm*64 + mf*16 + g + lohi*8;
                #pragma unroll
                for (int nf=0; nf<4; nf++){
                    int col = n0 + wn*32 + nf*8 + 2*t4;
                    float2 o;
                    o.x = acc[mf][nf][lohi*2+0] + bias[col];
                    o.y = acc[mf][nf][lohi*2+1] + bias[col+1];
                    *(float2*)&Co[(long)r*GG + col] = o;
                }
            }
    } else if (MODE==1){
        #pragma unroll
        for (int mf=0; mf<4; mf++)
            #pragma unroll
            for (int lohi=0; lohi<2; lohi++){
                int r = m0 + wm*64 + mf*16 + g + lohi*8;
                int rr = r - dir*2048;
                int m = rr>>5, b2 = rr&31;
                int tp = (ss==0)? TT : min(m+ss-1, TT-1);
                const float* xr = d_Pd + ((long)(dir*PDT+tp)*BB + b2)*GG;
                #pragma unroll
                for (int nf=0; nf<4; nf++){
                    int col = n0 + wn*32 + nf*8 + 2*t4;
                    float2 o;
                    o.x = acc[mf][nf][lohi*2+0] + xr[col];
                    o.y = acc[mf][nf][lohi*2+1] + xr[col+1];
                    *(float2*)&d_G[(long)r*GG + col] = o;
                }
            }
    } else {
        int nb = (n0>>5) + wn;
        #pragma unroll
        for (int mf=0; mf<4; mf++)
            #pragma unroll
            for (int lohi=0; lohi<2; lohi++){
                int r = m0 + wm*64 + mf*16 + g + lohi*8;
                float z[8]; float mx = NEGF;
                #pragma unroll
                for (int nf=0; nf<4; nf++)
                    #pragma unroll
                    for (int e=0; e<2; e++){
                        int v = n0 + wn*32 + nf*8 + 2*t4 + e;
                        float zz = acc[mf][nf][lohi*2+e] + ((v<VV)? bias[v] : NEGF);
                        z[nf*2+e] = zz;
                        mx = fmaxf(mx, zz);
                    }
                mx = fmaxf(mx, __shfl_xor_sync(0xffffffffu, mx, 1));
                mx = fmaxf(mx, __shfl_xor_sync(0xffffffffu, mx, 2));
                float sm = 0.f;
                #pragma unroll
                for (int j=0;j<8;j++) sm += __expf(z[j]-mx);
                sm += __shfl_xor_sync(0xffffffffu, sm, 1);
                sm += __shfl_xor_sync(0xffffffffu, sm, 2);
                if (t4 == 0 && nb < NP){
                    int srow = ss*NDROW + r;
                    d_part[((long)nb*SR + srow)*2    ] = mx;
                    d_part[((long)nb*SR + srow)*2 + 1] = sm;
                }
            }
    }
}

// ===================== tensor-core persistent encoder =====================
#define ESM_BYTES (64*520*2 + 2*64*136*2 + 64*66*4)
__global__ void __launch_bounds__(256) k_enc(const float* __restrict__ Whh){
    extern __shared__ char esm[];
    bf16* Ws  = (bf16*)esm;
    bf16* As  = Ws + 64*520;
    float* Gs = (float*)(As + 2*64*136);
    const int tid = threadIdx.x;
    const int h0 = blockIdx.x*16;

    {
        int c = tid>>2, t4w = tid&3;
        int gg = c&3, q = c>>2;
        const float* wr = Whh + (long)(gg*HH + h0 + q)*HH + t4w*128;
        bf16* dst = Ws + c*520 + t4w*128;
        #pragma unroll 4
        for (int j=0;j<128;j+=4){
            float4 v = *(const float4*)(wr+j);
            dst[j]   = __float2bfloat16_rn(v.x);
            dst[j+1] = __float2bfloat16_rn(v.y);
            dst[j+2] = __float2bfloat16_rn(v.z);
            dst[j+3] = __float2bfloat16_rn(v.w);
        }
    }
    __syncthreads();

    const int lane = tid&31, warp = tid>>5;
    const int wr4 = warp&3, wc = warp>>2;
    const int g = lane>>2, t4 = lane&3;
    const int rl = (lane&7) + ((lane>>3)&1)*8;
    const int ca = (lane>>4)*8;
    const int rb = (lane&7) + ((lane>>4)&1)*8;
    const int cb = ((lane>>3)&1)*8;
    const int srow = tid>>2, soff = (tid&3)*32;
    const int sdir = srow>>5, sb = srow&31;
    const int r = tid>>2, l4 = tid&3;
    const int dir = r>>5, b = r&31;

    float cst[4] = {0.f,0.f,0.f,0.f};
    unsigned gen = 0;

    for (int t=0; t<TT; t++){
        const bf16* hbase = d_HencB + ((long)(sdir*(TT+1)+t)*BB + sb)*HH + soff;
        {
            uint4 v0 = *(const uint4*)(hbase);
            uint4 v1 = *(const uint4*)(hbase+8);
            uint4 v2 = *(const uint4*)(hbase+16);
            uint4 v3 = *(const uint4*)(hbase+24);
            bf16* dst = As + srow*136 + soff;
            *(uint4*)dst = v0; *(uint4*)(dst+8) = v1;
            *(uint4*)(dst+16) = v2; *(uint4*)(dst+24) = v3;
        }
        __syncthreads();

        float acc[4][4];
        #pragma unroll
        for (int nf=0;nf<4;nf++)
            #pragma unroll
            for (int e=0;e<4;e++) acc[nf][e]=0.f;

        #pragma unroll 1
        for (int c4=0; c4<4; c4++){
            uint4 v0,v1,v2,v3;
            if (c4+1 < 4){
                const bf16* src = hbase + (c4+1)*128;
                v0 = *(const uint4*)(src); v1 = *(const uint4*)(src+8);
                v2 = *(const uint4*)(src+16); v3 = *(const uint4*)(src+24);
            }
            const bf16* Ab = As + (c4&1)*64*136;
            const int kc = c4*128;
            #pragma unroll
            for (int ks=0; ks<128; ks+=16){
                unsigned af[4], bfm[2][4];
                ldsm4(af, sptr(Ab + (16*wr4+rl)*136 + ks + ca));
                #pragma unroll
                for (int p=0;p<2;p++)
                    ldsm4(bfm[p], sptr(Ws + (wc*32+p*16+rb)*520 + kc + ks + cb));
                #pragma unroll
                for (int nf=0;nf<4;nf++)
                    mma16(acc[nf], af, &bfm[nf>>1][(nf&1)*2]);
            }
            __syncthreads();
            if (c4+1 < 4){
                bf16* dst = As + ((c4+1)&1)*64*136 + srow*136 + soff;
                *(uint4*)dst = v0; *(uint4*)(dst+8) = v1;
                *(uint4*)(dst+16) = v2; *(uint4*)(dst+24) = v3;
                __syncthreads();
            }
        }
        #pragma unroll
        for (int nf=0;nf<4;nf++){
            int col = wc*32 + nf*8 + 2*t4;
            Gs[(16*wr4+g)*66 + col]   = acc[nf][0];
            Gs[(16*wr4+g)*66 + col+1] = acc[nf][1];
            Gs[(16*wr4+g+8)*66 + col]   = acc[nf][2];
            Gs[(16*wr4+g+8)*66 + col+1] = acc[nf][3];
        }
        __syncthreads();
        {
            const float* xb = d_Xe + (long)(t*ROWS_E + r)*GG;
            #pragma unroll
            for (int j=0;j<4;j++){
                int q = l4 + 4*j; int h = h0 + q;
                float gi = Gs[r*66 + 4*q + 0] + xb[h];
                float gf = Gs[r*66 + 4*q + 1] + xb[HH+h];
                float g2 = Gs[r*66 + 4*q + 2] + xb[2*HH+h];
                float go = Gs[r*66 + 4*q + 3] + xb[3*HH+h];
                cst[j] = sigm(gf)*cst[j] + sigm(gi)*tanhf(g2);
                float hn = sigm(go)*tanhf(cst[j]);
                long oi = ((long)(dir*(TT+1)+(t+1))*BB + b)*HH + h;
                d_Henc[oi]  = hn;
                d_HencB[oi] = __float2bfloat16_rn(hn);
            }
        }
        __threadfence();
        __syncthreads();
        if (tid==0){
            unsigned a = atomicAdd(&g_cnt, 1u);
            if (a == gridDim.x-1){
                g_cnt = 0;
                __threadfence();
                atomicExch(&g_gen, gen+1u);
            } else {
                while (*((volatile unsigned*)&g_gen) != gen+1u) __nanosleep(32);
                __threadfence();
            }
        }
        __syncthreads();
        gen++;
    }
}

// ----- decoder init -----
__global__ void k_decinit(){
    int i = blockIdx.x*blockDim.x + threadIdx.x;
    int row = i>>9, h = i&511;
    int dir = row>>11, rr = row&2047, m = rr>>5, b = rr&31;
    float v = d_Henc[((long)(dir*(TT+1)+(m+1))*BB+b)*HH + h];
    d_Hdec[i] = v;
    d_Cdec[i] = v;
    d_HdecB[i] = __float2bfloat16_rn(v);
}

// ----- decoder cell -----
__global__ void k_cell(int s){
    int i = blockIdx.x*blockDim.x + threadIdx.x;
    int row = i>>9, h = i&511;
    const float* gr = d_G + (long)row*GG;
    float gi = gr[h], gf = gr[HH+h], g2 = gr[2*HH+h], go = gr[3*HH+h];
    float cp = d_Cdec[(s&1)*NDROW*HH + i];
    float c = sigm(gf)*cp + sigm(gi)*tanhf(g2);
    float hn = sigm(go)*tanhf(c);
    d_Cdec[((s+1)&1)*NDROW*HH + i] = c;
    d_Hdec[(s+1)*NDROW*HH + i] = hn;
    d_HdecB[(long)(s+1)*NDROW*HH + i] = __float2bfloat16_rn(hn);
}

// ----- gathered picks (bf16 inputs, fp32 accumulate) -----
__global__ void k_picks(const float* __restrict__ fhb, const float* __restrict__ bhb){
    int w = (blockIdx.x*blockDim.x + threadIdx.x) >> 5;
    int lane = threadIdx.x & 31;
    if (w >= 6*NDROW) return;
    int kind = w / NDROW;
    int row  = w % NDROW;
    int dir = row>>11, rr = row&2047, m = rr>>5, b = rr&31;
    const bf16* hW = dir ? d_hWbB : d_hWfB;
    const float* hb = dir ? bhb : fhb;
    int s, y;
    if (kind < 3){ s = kind;   y = d_tokD[dir*PDROWS + min(m+s, TT-1)*BB + b]; }
    else         { s = kind-2; y = 0; }
    const bf16* h = d_HdecB + (long)(s+1)*NDROW*HH + (long)row*HH;
    const bf16* wv = hW + (long)y*HH;
    float sum = 0.f;
    #pragma unroll 4
    for (int k=lane*2; k<HH; k+=64){
        __nv_bfloat162 a = *(const __nv_bfloat162*)(h+k);
        __nv_bfloat162 x = *(const __nv_bfloat162*)(wv+k);
        sum += __bfloat162float(a.x)*__bfloat162float(x.x)
             + __bfloat162float(a.y)*__bfloat162float(x.y);
    }
    #pragma unroll
    for (int off=16; off; off>>=1) sum += __shfl_xor_sync(0xffffffffu, sum, off);
    if (!lane){
        if (kind < 3) d_zc[s*NDROW + row] = sum + hb[y];
        else          d_zt[s*NDROW + row] = sum + hb[0];
    }
}

// ----- combine LSE partials -----
__global__ void k_lse2(){
    int i = blockIdx.x*blockDim.x + threadIdx.x;
    if (i >= SR) return;
    float mx = NEGF, sm = 0.f;
    for (int nb=0; nb<NP; nb++){
        float2 p = *(float2*)&d_part[((long)nb*SR + i)*2];
        if (p.x > mx){ sm = sm*__expf(mx-p.x) + p.y; mx = p.x; }
        else sm += p.y*__expf(p.x-mx);
    }
    d_lse[i] = mx + logf(sm);
}

// ----- segment scores -----
__global__ void k_res(){
    int i = blockIdx.x*blockDim.x + threadIdx.x;
    if (i >= NDROW) return;
    int dir = i>>11, rr = i&2047, m = rr>>5, b = rr&31;
    float cum = 0.f;
    #pragma unroll
    for (int l=0; l<WW; l++){
        cum += d_zc[l*NDROW+i] - d_lse[l*NDROW+i];
        float tg = d_zt[(l+1)*NDROW+i] - d_lse[(l+1)*NDROW+i];
        d_res[((dir*TT+m)*WW+l)*BB + b] = cum + tg;
    }
}

// ----- final DP -----
__global__ void k_final(float* __restrict__ out){
    int b = threadIdx.x;
    float w0 = 0.f, w1 = NEGF, w2 = NEGF;
    for (int e=0; e<TT; e++){
        float p[3];
        #pragma unroll
        for (int l=0; l<3; l++){
            int st = e - l;
            p[l] = (st >= 0) ? (d_res[((0*TT+st)*WW+l)*BB + b]
                              + d_res[((1*TT+(TT-1-e))*WW+l)*BB + b]) : NEGF;
        }
        float x0 = w0+p[0], x1 = w1+p[1], x2 = w2+p[2];
        float m = fmaxf(x0, fmaxf(x1, x2));
        float tot = m + logf(__expf(x0-m) + __expf(x1-m) + __expf(x2-m));
        w2 = w1; w1 = w0; w0 = tot;
    }
    float v = w0;
    #pragma unroll
    for (int off=16; off; off>>=1) v += __shfl_xor_sync(0xffffffffu, v, off);
    if (b == 0) out[0] = -v/(float)BB;
}

extern "C" void kernel_launch(void* const* d_in, const int* in_sizes, int n_in,
                              void* d_out, int out_size){
    const int*   sent = (const int*)  d_in[0];
    const float* emb  = (const float*)d_in[1];
    const float* eWih = (const float*)d_in[2];
    const float* eWhh = (const float*)d_in[3];
    const float* eB   = (const float*)d_in[4];
    const float* fWih = (const float*)d_in[5];
    const float* fWhh = (const float*)d_in[6];
    const float* fB   = (const float*)d_in[7];
    const float* fhW  = (const float*)d_in[8];
    const float* fhb  = (const float*)d_in[9];
    const float* bWih = (const float*)d_in[10];
    const float* bWhh = (const float*)d_in[11];
    const float* bB   = (const float*)d_in[12];
    const float* bhW  = (const float*)d_in[13];
    const float* bhb  = (const float*)d_in[14];
    float* out = (float*)d_out;

    cudaFuncSetAttribute(k_enc, cudaFuncAttributeMaxDynamicSharedMemorySize, ESM_BYTES);
    cudaFuncSetAttribute(k_bgemm<0>, cudaFuncAttributeMaxDynamicSharedMemorySize, BG_SMEM);
    cudaFuncSetAttribute(k_bgemm<1>, cudaFuncAttributeMaxDynamicSharedMemorySize, BG_SMEM);
    cudaFuncSetAttribute(k_bgemm<2>, cudaFuncAttributeMaxDynamicSharedMemorySize, BG_SMEM);

    k_init<<<128,256>>>(sent);
    {
        long nA = (long)VV*EE + 3L*GG*EE;
        long nB = 2L*GG*HH + 2L*VV*HH;
        k_convA<<<(int)((nA/4+255)/256),256>>>(emb, eWih, fWih, bWih);
        k_convB<<<(int)((nB/4+255)/256),256>>>(fWhh, bWhh, fhW, bhW);
    }
    k_bgemm<0><<<dim3(16,32,1),256,BG_SMEM>>>(eB, eB, 0, 1<<30, 0);
    k_bgemm<0><<<dim3(16,34,1),256,BG_SMEM>>>(fB, bB, 1, PDROWS, 0);
    k_enc<<<32,256,ESM_BYTES>>>(eWhh);                        // 6th launch -> ncu target
    k_decinit<<<8192,256>>>();
    for (int s=0; s<4; s++){
        k_bgemm<1><<<dim3(16,32,1),256,BG_SMEM>>>(0, 0, 0, 2048, s);
        k_cell<<<4096,512>>>(s);
    }
    k_picks<<<3072,256>>>(fhb, bhb);
    k_bgemm<2><<<dim3(63,32,4),256,BG_SMEM>>>(fhb, bhb, 0, 2048, 0);
    k_lse2<<<64,256>>>();
    k_res<<<16,256>>>();
    k_final<<<1,32>>>(out);
}

// round 8
// speedup vs baseline: 4.6870x; 1.0059x over previous
#include <cuda_runtime.h>
#include <cuda_bf16.h>
#include <stdint.h>
#include <math.h>

#define BB 32
#define TT 64
#define VV 8000
#define EE 256
#define HH 512
#define GG 2048
#define WW 3
#define NEGF (-1e30f)
#define NDROW 4096
#define ROWS_E 64
#define PDT 68
#define PDROWS (PDT*BB)      // 2176
#define NP 250               // vocab partial strips of 32
#define SR (4*NDROW)

typedef __nv_bfloat16 bf16;

// ----- fp32 scratch -----
__device__ float d_Xe[TT*ROWS_E*GG];
__device__ float d_Henc[2*(TT+1)*BB*HH];
__device__ float d_Pd[2*PDROWS*GG];
__device__ float d_G[NDROW*GG];
__device__ float d_Hdec[5*NDROW*HH];
__device__ float d_Cdec[2*NDROW*HH];
__device__ int   d_tokE[TT*ROWS_E];
__device__ int   d_tokD[2*PDROWS];
__device__ float d_zc[3*NDROW];
__device__ float d_zt[4*NDROW];
__device__ float d_part[NP*SR*2];
__device__ float d_lse[4*NDROW];
__device__ float d_res[2*TT*WW*BB];
__device__ unsigned g_cnt;
__device__ unsigned g_gen;

// ----- bf16 mirrors -----
__device__ bf16 d_embB[VV*EE];
__device__ bf16 d_WeIB[GG*EE];
__device__ bf16 d_WfIB[GG*EE];
__device__ bf16 d_WbIB[GG*EE];
__device__ bf16 d_WfHB[GG*HH];
__device__ bf16 d_WbHB[GG*HH];
__device__ bf16 d_hWfB[VV*HH];
__device__ bf16 d_hWbB[VV*HH];
__device__ bf16 d_HencB[2*(TT+1)*BB*HH];
__device__ bf16 d_HdecB[5*NDROW*HH];

__device__ __forceinline__ float sigm(float x){ return 1.f/(1.f+__expf(-x)); }
__device__ __forceinline__ unsigned sptr(const void* p){
    return (unsigned)__cvta_generic_to_shared(p);
}
__device__ __forceinline__ void ldsm4(unsigned* r, unsigned a){
    asm volatile("ldmatrix.sync.aligned.m8n8.x4.shared.b16 {%0,%1,%2,%3}, [%4];\n"
        : "=r"(r[0]),"=r"(r[1]),"=r"(r[2]),"=r"(r[3]) : "r"(a));
}
__device__ __forceinline__ void mma16(float* c, const unsigned* a, const unsigned* b){
    asm volatile("mma.sync.aligned.m16n8k16.row.col.f32.bf16.bf16.f32 "
        "{%0,%1,%2,%3},{%4,%5,%6,%7},{%8,%9},{%0,%1,%2,%3};\n"
        : "+f"(c[0]),"+f"(c[1]),"+f"(c[2]),"+f"(c[3])
        : "r"(a[0]),"r"(a[1]),"r"(a[2]),"r"(a[3]),"r"(b[0]),"r"(b[1]));
}
__device__ __forceinline__ void cp16(unsigned dst, const void* src, int ssz){
    asm volatile("cp.async.cg.shared.global [%0], [%1], 16, %2;\n"
        :: "r"(dst), "l"(src), "r"(ssz));
}

// ----- fp32 -> bf16 conversion (2 merged kernels) -----
__global__ void k_convA(const float* __restrict__ emb, const float* __restrict__ eWih,
                        const float* __restrict__ fWih, const float* __restrict__ bWih){
    const long n0 = (long)VV*EE, n1 = n0 + (long)GG*EE, n2 = n1 + (long)GG*EE, n3 = n2 + (long)GG*EE;
    long i = ((long)blockIdx.x*blockDim.x + threadIdx.x)*4;
    if (i >= n3) return;
    const float* src; bf16* dst; long off;
    if (i < n0){ src=emb; dst=d_embB; off=i; }
    else if (i < n1){ src=eWih; dst=d_WeIB; off=i-n0; }
    else if (i < n2){ src=fWih; dst=d_WfIB; off=i-n1; }
    else { src=bWih; dst=d_WbIB; off=i-n2; }
    float4 v = *(const float4*)(src+off);
    *(__nv_bfloat162*)(dst+off)   = __floats2bfloat162_rn(v.x, v.y);
    *(__nv_bfloat162*)(dst+off+2) = __floats2bfloat162_rn(v.z, v.w);
}
__global__ void k_convB(const float* __restrict__ fWhh, const float* __restrict__ bWhh,
                        const float* __restrict__ fhW, const float* __restrict__ bhW){
    const long n0 = (long)GG*HH, n1 = n0 + (long)GG*HH, n2 = n1 + (long)VV*HH, n3 = n2 + (long)VV*HH;
    long i = ((long)blockIdx.x*blockDim.x + threadIdx.x)*4;
    if (i >= n3) return;
    const float* src; bf16* dst; long off;
    if (i < n0){ src=fWhh; dst=d_WfHB; off=i; }
    else if (i < n1){ src=bWhh; dst=d_WbHB; off=i-n0; }
    else if (i < n2){ src=fhW; dst=d_hWfB; off=i-n1; }
    else { src=bhW; dst=d_hWbB; off=i-n2; }
    float4 v = *(const float4*)(src+off);
    *(__nv_bfloat162*)(dst+off)   = __floats2bfloat162_rn(v.x, v.y);
    *(__nv_bfloat162*)(dst+off+2) = __floats2bfloat162_rn(v.z, v.w);
}

// ----- init -----
__global__ void k_init(const int* __restrict__ sent){
    int i = blockIdx.x*blockDim.x + threadIdx.x;
    if (i == 0){ g_cnt = 0u; g_gen = 0u; }
    if (i < 2*BB*HH){
        int dir = i/(BB*HH); int rem = i%(BB*HH);
        d_HencB[(dir*(TT+1))*BB*HH + rem] = __float2bfloat16(0.f);
    }
    if (i < TT*ROWS_E){
        int t = i/ROWS_E, r = i%ROWS_E, dir = r/BB, b = r%BB;
        int tok = (t==0) ? 0 : (dir ? sent[b*TT + (TT-t)] : sent[b*TT + (t-1)]);
        d_tokE[i] = tok;
    }
    if (i < 2*PDROWS){
        int dir = i/PDROWS; int rem = i%PDROWS; int t = rem/BB, b = rem%BB;
        int tok = (t < TT) ? (dir ? sent[b*TT + (TT-1-t)] : sent[b*TT + t]) : 0;
        d_tokD[i] = tok;
    }
}

// ===================== bf16 mma.sync GEMM, K-chunk 64, 3-stage cp.async =====================
// stage layout (halves): [st*18432 .. ]: A 128x72, then B 128x72 at +9216
#define BG_SMEM (3*36864)     // 110592 bytes
extern __shared__ bf16 dynsm[];

template<int MODE>
__global__ void __launch_bounds__(256,2) k_bgemm(
    const float* __restrict__ bias0, const float* __restrict__ bias1,
    int gsel, int mhalf, int s)
{
    constexpr int KD = (MODE==0)? EE : HH;
    constexpr int NC = KD/64;
    const int tid = threadIdx.x;
    const int m0 = blockIdx.y*128, n0 = blockIdx.x*128;
    const int ss = (MODE==2)? (int)blockIdx.z : s;
    const int dir = (m0 >= mhalf)? 1 : 0;
    const bf16* Bm;
    if (MODE==0) Bm = gsel? (dir? d_WbIB : d_WfIB) : d_WeIB;
    else if (MODE==1) Bm = dir? d_WbHB : d_WfHB;
    else Bm = dir? d_hWbB : d_hWfB;
    const float* bias = dir? bias1 : bias0;

    const int lrow = tid>>1, lhalf = (tid&1)*32;
    const bf16* arow;
    if (MODE==0){
        const int* tok = gsel? d_tokD : d_tokE;
        arow = d_embB + (long)tok[m0+lrow]*KD;
    } else if (MODE==1){
        arow = d_HdecB + (long)ss*NDROW*HH + (long)(m0+lrow)*HH;
    } else {
        arow = d_HdecB + (long)(ss+1)*NDROW*HH + (long)(m0+lrow)*HH;
    }
    const int vrow = n0 + lrow;
    const bool bval = (MODE!=2) || (vrow < VV);
    const bf16* brow = Bm + (long)(bval? vrow : 0)*KD;
    const int bok = bval? 16 : 0;

    const unsigned smB0 = sptr(dynsm);
    const unsigned ldoff = (unsigned)((lrow*72 + lhalf)*2);

    auto issue_chunk = [&](int kt, int st){
        int k0 = kt*64;
        unsigned base = smB0 + (unsigned)st*36864u;
        const bf16* as = arow + k0 + lhalf;
        unsigned adst = base + ldoff;
        cp16(adst,     as,    16); cp16(adst+16u, as+8,  16);
        cp16(adst+32u, as+16, 16); cp16(adst+48u, as+24, 16);
        const bf16* bs = brow + k0 + lhalf;
        unsigned bdst = base + 18432u + ldoff;
        cp16(bdst,     bs,    bok); cp16(bdst+16u, bs+8,  bok);
        cp16(bdst+32u, bs+16, bok); cp16(bdst+48u, bs+24, bok);
        asm volatile("cp.async.commit_group;" ::: "memory");
    };

    const int lane = tid&31, warp = tid>>5;
    const int wm = warp&1, wn = warp>>1;
    const int g = lane>>2, t4 = lane&3;
    const int rl = (lane&7) + ((lane>>3)&1)*8;
    const int ca = (lane>>4)*8;
    const int rb = (lane&7) + ((lane>>4)&1)*8;
    const int cb = ((lane>>3)&1)*8;

    float acc[4][4][4];
    #pragma unroll
    for (int i=0;i<4;i++)
        #pragma unroll
        for (int j=0;j<4;j++)
            #pragma unroll
            for (int e=0;e<4;e++) acc[i][j][e]=0.f;

    issue_chunk(0, 0);
    issue_chunk(1, 1);

    #pragma unroll 1
    for (int kt=0; kt<NC; kt++){
        asm volatile("cp.async.wait_group 1;" ::: "memory");
        __syncthreads();
        int nx = kt + 2;
        if (nx < NC) issue_chunk(nx, nx%3);
        else asm volatile("cp.async.commit_group;" ::: "memory");
        const bf16* Ab = dynsm + (kt%3)*18432;
        const bf16* Bb = Ab + 9216;
        #pragma unroll
        for (int ks=0; ks<64; ks+=16){
            unsigned af[4][4], bfm[2][4];
            #pragma unroll
            for (int mf=0;mf<4;mf++)
                ldsm4(af[mf], sptr(Ab + (wm*64+mf*16+rl)*72 + ks + ca));
            #pragma unroll
            for (int p=0;p<2;p++)
                ldsm4(bfm[p], sptr(Bb + (wn*32+p*16+rb)*72 + ks + cb));
            #pragma unroll
            for (int mf=0;mf<4;mf++)
                #pragma unroll
                for (int nf=0;nf<4;nf++)
                    mma16(acc[mf][nf], af[mf], &bfm[nf>>1][(nf&1)*2]);
        }
    }

    if (MODE==0){
        float* Co = gsel? d_Pd : d_Xe;
        #pragma unroll
        for (int mf=0; mf<4; mf++)
            #pragma unroll
            for (int lohi=0; lohi<2; lohi++){
                int r = m0 + wm*64 + mf*16 + g + lohi*8;
                #pragma unroll
                for (int nf=0; nf<4; nf++){
                    int col = n0 + wn*32 + nf*8 + 2*t4;
                    float2 o;
                    o.x = acc[mf][nf][lohi*2+0] + bias[col];
                    o.y = acc[mf][nf][lohi*2+1] + bias[col+1];
                    *(float2*)&Co[(long)r*GG + col] = o;
                }
            }
    } else if (MODE==1){
        #pragma unroll
        for (int mf=0; mf<4; mf++)
            #pragma unroll
            for (int lohi=0; lohi<2; lohi++){
                int r = m0 + wm*64 + mf*16 + g + lohi*8;
                int rr = r - dir*2048;
                int m = rr>>5, b2 = rr&31;
                int tp = (ss==0)? TT : min(m+ss-1, TT-1);
                const float* xr = d_Pd + ((long)(dir*PDT+tp)*BB + b2)*GG;
                #pragma unroll
                for (int nf=0; nf<4; nf++){
                    int col = n0 + wn*32 + nf*8 + 2*t4;
                    float2 o;
                    o.x = acc[mf][nf][lohi*2+0] + xr[col];
                    o.y = acc[mf][nf][lohi*2+1] + xr[col+1];
                    *(float2*)&d_G[(long)r*GG + col] = o;
                }
            }
    } else {
        int nb = (n0>>5) + wn;
        #pragma unroll
        for (int mf=0; mf<4; mf++)
            #pragma unroll
            for (int lohi=0; lohi<2; lohi++){
                int r = m0 + wm*64 + mf*16 + g + lohi*8;
                float z[8]; float mx = NEGF;
                #pragma unroll
                for (int nf=0; nf<4; nf++)
                    #pragma unroll
                    for (int e=0; e<2; e++){
                        int v = n0 + wn*32 + nf*8 + 2*t4 + e;
                        float zz = acc[mf][nf][lohi*2+e] + ((v<VV)? bias[v] : NEGF);
                        z[nf*2+e] = zz;
                        mx = fmaxf(mx, zz);
                    }
                mx = fmaxf(mx, __shfl_xor_sync(0xffffffffu, mx, 1));
                mx = fmaxf(mx, __shfl_xor_sync(0xffffffffu, mx, 2));
                float sm = 0.f;
                #pragma unroll
                for (int j=0;j<8;j++) sm += __expf(z[j]-mx);
                sm += __shfl_xor_sync(0xffffffffu, sm, 1);
                sm += __shfl_xor_sync(0xffffffffu, sm, 2);
                if (t4 == 0 && nb < NP){
                    int srow = ss*NDROW + r;
                    d_part[((long)nb*SR + srow)*2    ] = mx;
                    d_part[((long)nb*SR + srow)*2 + 1] = sm;
                }
            }
    }
}

// ===================== tensor-core persistent encoder (full-H cp.async stage) =====================
// smem: Ws[64][520] bf16 + As[64][520] bf16 + Gs[64][66] f32
#define ESM_BYTES (64*520*2 + 64*520*2 + 64*66*4)
__global__ void __launch_bounds__(256) k_enc(const float* __restrict__ Whh){
    extern __shared__ char esm[];
    bf16* Ws  = (bf16*)esm;
    bf16* As  = Ws + 64*520;
    float* Gs = (float*)(As + 64*520);
    const int tid = threadIdx.x;
    const int h0 = blockIdx.x*16;

    {   // load + convert Whh slice, permuted: col c=4q+g <- Whh row g*512+h0+q
        int c = tid>>2, t4w = tid&3;
        int gg = c&3, q = c>>2;
        const float* wr = Whh + (long)(gg*HH + h0 + q)*HH + t4w*128;
        bf16* dst = Ws + c*520 + t4w*128;
        #pragma unroll 4
        for (int j=0;j<128;j+=4){
            float4 v = *(const float4*)(wr+j);
            dst[j]   = __float2bfloat16_rn(v.x);
            dst[j+1] = __float2bfloat16_rn(v.y);
            dst[j+2] = __float2bfloat16_rn(v.z);
            dst[j+3] = __float2bfloat16_rn(v.w);
        }
    }
    __syncthreads();

    const int lane = tid&31, warp = tid>>5;
    const int wr4 = warp&3, wc = warp>>2;
    const int g = lane>>2, t4 = lane&3;
    const int rl = (lane&7) + ((lane>>3)&1)*8;
    const int ca = (lane>>4)*8;
    const int rb = (lane&7) + ((lane>>4)&1)*8;
    const int cb = ((lane>>3)&1)*8;
    const int srow = tid>>2, qd = tid&3;          // staging: row, quarter
    const int sdir = srow>>5, sb = srow&31;
    const int r = tid>>2, l4 = tid&3;
    const int dir = r>>5, b = r&31;

    const unsigned asbase = sptr(As) + (unsigned)((srow*520 + qd*128)*2);

    float cst[4] = {0.f,0.f,0.f,0.f};
    unsigned gen = 0;

    for (int t=0; t<TT; t++){
        // stage whole H (64x512 bf16) via cp.async: 16x 16B per thread
        {
            const bf16* src = d_HencB + ((long)(sdir*(TT+1)+t)*BB + sb)*HH + qd*128;
            #pragma unroll
            for (int i=0;i<16;i++) cp16(asbase + i*16u, src + i*8, 16);
            asm volatile("cp.async.commit_group;" ::: "memory");
            asm volatile("cp.async.wait_group 0;" ::: "memory");
        }
        __syncthreads();

        float acc[4][4];
        #pragma unroll
        for (int nf=0;nf<4;nf++)
            #pragma unroll
            for (int e=0;e<4;e++) acc[nf][e]=0.f;

        #pragma unroll 4
        for (int ks=0; ks<512; ks+=16){
            unsigned af[4], bfm[2][4];
            ldsm4(af, sptr(As + (16*wr4+rl)*520 + ks + ca));
            #pragma unroll
            for (int p=0;p<2;p++)
                ldsm4(bfm[p], sptr(Ws + (wc*32+p*16+rb)*520 + ks + cb));
            #pragma unroll
            for (int nf=0;nf<4;nf++)
                mma16(acc[nf], af, &bfm[nf>>1][(nf&1)*2]);
        }
        // stage gates
        #pragma unroll
        for (int nf=0;nf<4;nf++){
            int col = wc*32 + nf*8 + 2*t4;
            Gs[(16*wr4+g)*66 + col]   = acc[nf][0];
            Gs[(16*wr4+g)*66 + col+1] = acc[nf][1];
            Gs[(16*wr4+g+8)*66 + col]   = acc[nf][2];
            Gs[(16*wr4+g+8)*66 + col+1] = acc[nf][3];
        }
        __syncthreads();
        // cell update: thread handles (r, h0 + l4 + 4j)
        {
            const float* xb = d_Xe + (long)(t*ROWS_E + r)*GG;
            #pragma unroll
            for (int j=0;j<4;j++){
                int q = l4 + 4*j; int h = h0 + q;
                float gi = Gs[r*66 + 4*q + 0] + xb[h];
                float gf = Gs[r*66 + 4*q + 1] + xb[HH+h];
                float g2 = Gs[r*66 + 4*q + 2] + xb[2*HH+h];
                float go = Gs[r*66 + 4*q + 3] + xb[3*HH+h];
                cst[j] = sigm(gf)*cst[j] + sigm(gi)*tanhf(g2);
                float hn = sigm(go)*tanhf(cst[j]);
                long oi = ((long)(dir*(TT+1)+(t+1))*BB + b)*HH + h;
                d_Henc[oi]  = hn;
                d_HencB[oi] = __float2bfloat16_rn(hn);
            }
        }
        // grid barrier
        __threadfence();
        __syncthreads();
        if (tid==0){
            unsigned a = atomicAdd(&g_cnt, 1u);
            if (a == gridDim.x-1){
                g_cnt = 0;
                __threadfence();
                atomicExch(&g_gen, gen+1u);
            } else {
                while (*((volatile unsigned*)&g_gen) != gen+1u) __nanosleep(32);
                __threadfence();
            }
        }
        __syncthreads();
        gen++;
    }
}

// ----- decoder init -----
__global__ void k_decinit(){
    int i = blockIdx.x*blockDim.x + threadIdx.x;
    int row = i>>9, h = i&511;
    int dir = row>>11, rr = row&2047, m = rr>>5, b = rr&31;
    float v = d_Henc[((long)(dir*(TT+1)+(m+1))*BB+b)*HH + h];
    d_Hdec[i] = v;
    d_Cdec[i] = v;
    d_HdecB[i] = __float2bfloat16_rn(v);
}

// ----- decoder cell -----
__global__ void k_cell(int s){
    int i = blockIdx.x*blockDim.x + threadIdx.x;
    int row = i>>9, h = i&511;
    const float* gr = d_G + (long)row*GG;
    float gi = gr[h], gf = gr[HH+h], g2 = gr[2*HH+h], go = gr[3*HH+h];
    float cp = d_Cdec[(s&1)*NDROW*HH + i];
    float c = sigm(gf)*cp + sigm(gi)*tanhf(g2);
    float hn = sigm(go)*tanhf(c);
    d_Cdec[((s+1)&1)*NDROW*HH + i] = c;
    d_Hdec[(s+1)*NDROW*HH + i] = hn;
    d_HdecB[(long)(s+1)*NDROW*HH + i] = __float2bfloat16_rn(hn);
}

// ----- gathered picks (bf16 inputs, fp32 accumulate) -----
__global__ void k_picks(const float* __restrict__ fhb, const float* __restrict__ bhb){
    int w = (blockIdx.x*blockDim.x + threadIdx.x) >> 5;
    int lane = threadIdx.x & 31;
    if (w >= 6*NDROW) return;
    int kind = w / NDROW;
    int row  = w % NDROW;
    int dir = row>>11, rr = row&2047, m = rr>>5, b = rr&31;
    const bf16* hW = dir ? d_hWbB : d_hWfB;
    const float* hb = dir ? bhb : fhb;
    int s, y;
    if (kind < 3){ s = kind;   y = d_tokD[dir*PDROWS + min(m+s, TT-1)*BB + b]; }
    else         { s = kind-2; y = 0; }
    const bf16* h = d_HdecB + (long)(s+1)*NDROW*HH + (long)row*HH;
    const bf16* wv = hW + (long)y*HH;
    float sum = 0.f;
    #pragma unroll 4
    for (int k=lane*2; k<HH; k+=64){
        __nv_bfloat162 a = *(const __nv_bfloat162*)(h+k);
        __nv_bfloat162 x = *(const __nv_bfloat162*)(wv+k);
        sum += __bfloat162float(a.x)*__bfloat162float(x.x)
             + __bfloat162float(a.y)*__bfloat162float(x.y);
    }
    #pragma unroll
    for (int off=16; off; off>>=1) sum += __shfl_xor_sync(0xffffffffu, sum, off);
    if (!lane){
        if (kind < 3) d_zc[s*NDROW + row] = sum + hb[y];
        else          d_zt[s*NDROW + row] = sum + hb[0];
    }
}

// ----- combine LSE partials -----
__global__ void k_lse2(){
    int i = blockIdx.x*blockDim.x + threadIdx.x;
    if (i >= SR) return;
    float mx = NEGF, sm = 0.f;
    for (int nb=0; nb<NP; nb++){
        float2 p = *(float2*)&d_part[((long)nb*SR + i)*2];
        if (p.x > mx){ sm = sm*__expf(mx-p.x) + p.y; mx = p.x; }
        else sm += p.y*__expf(p.x-mx);
    }
    d_lse[i] = mx + logf(sm);
}

// ----- segment scores -----
__global__ void k_res(){
    int i = blockIdx.x*blockDim.x + threadIdx.x;
    if (i >= NDROW) return;
    int dir = i>>11, rr = i&2047, m = rr>>5, b = rr&31;
    float cum = 0.f;
    #pragma unroll
    for (int l=0; l<WW; l++){
        cum += d_zc[l*NDROW+i] - d_lse[l*NDROW+i];
        float tg = d_zt[(l+1)*NDROW+i] - d_lse[(l+1)*NDROW+i];
        d_res[((dir*TT+m)*WW+l)*BB + b] = cum + tg;
    }
}

// ----- final DP -----
__global__ void k_final(float* __restrict__ out){
    int b = threadIdx.x;
    float w0 = 0.f, w1 = NEGF, w2 = NEGF;
    for (int e=0; e<TT; e++){
        float p[3];
        #pragma unroll
        for (int l=0; l<3; l++){
            int st = e - l;
            p[l] = (st >= 0) ? (d_res[((0*TT+st)*WW+l)*BB + b]
                              + d_res[((1*TT+(TT-1-e))*WW+l)*BB + b]) : NEGF;
        }
        float x0 = w0+p[0], x1 = w1+p[1], x2 = w2+p[2];
        float m = fmaxf(x0, fmaxf(x1, x2));
        float tot = m + logf(__expf(x0-m) + __expf(x1-m) + __expf(x2-m));
        w2 = w1; w1 = w0; w0 = tot;
    }
    float v = w0;
    #pragma unroll
    for (int off=16; off; off>>=1) v += __shfl_xor_sync(0xffffffffu, v, off);
    if (b == 0) out[0] = -v/(float)BB;
}

extern "C" void kernel_launch(void* const* d_in, const int* in_sizes, int n_in,
                              void* d_out, int out_size){
    const int*   sent = (const int*)  d_in[0];
    const float* emb  = (const float*)d_in[1];
    const float* eWih = (const float*)d_in[2];
    const float* eWhh = (const float*)d_in[3];
    const float* eB   = (const float*)d_in[4];
    const float* fWih = (const float*)d_in[5];
    const float* fWhh = (const float*)d_in[6];
    const float* fB   = (const float*)d_in[7];
    const float* fhW  = (const float*)d_in[8];
    const float* fhb  = (const float*)d_in[9];
    const float* bWih = (const float*)d_in[10];
    const float* bWhh = (const float*)d_in[11];
    const float* bB   = (const float*)d_in[12];
    const float* bhW  = (const float*)d_in[13];
    const float* bhb  = (const float*)d_in[14];
    float* out = (float*)d_out;

    cudaFuncSetAttribute(k_enc, cudaFuncAttributeMaxDynamicSharedMemorySize, ESM_BYTES);
    cudaFuncSetAttribute(k_bgemm<0>, cudaFuncAttributeMaxDynamicSharedMemorySize, BG_SMEM);
    cudaFuncSetAttribute(k_bgemm<1>, cudaFuncAttributeMaxDynamicSharedMemorySize, BG_SMEM);
    cudaFuncSetAttribute(k_bgemm<2>, cudaFuncAttributeMaxDynamicSharedMemorySize, BG_SMEM);

    k_init<<<128,256>>>(sent);
    {
        long nA = (long)VV*EE + 3L*GG*EE;
        long nB = 2L*GG*HH + 2L*VV*HH;
        k_convA<<<(int)((nA/4+255)/256),256>>>(emb, eWih, fWih, bWih);
        k_convB<<<(int)((nB/4+255)/256),256>>>(fWhh, bWhh, fhW, bhW);
    }
    k_bgemm<0><<<dim3(16,32,1),256,BG_SMEM>>>(eB, eB, 0, 1<<30, 0);
    k_bgemm<0><<<dim3(16,34,1),256,BG_SMEM>>>(fB, bB, 1, PDROWS, 0);
    k_enc<<<32,256,ESM_BYTES>>>(eWhh);                        // 6th launch -> ncu target
    k_decinit<<<8192,256>>>();
    for (int s=0; s<4; s++){
        k_bgemm<1><<<dim3(16,32,1),256,BG_SMEM>>>(0, 0, 0, 2048, s);
        k_cell<<<4096,512>>>(s);
    }
    k_picks<<<3072,256>>>(fhb, bhb);
    k_bgemm<2><<<dim3(63,32,4),256,BG_SMEM>>>(fhb, bhb, 0, 2048, 0);
    k_lse2<<<64,256>>>();
    k_res<<<16,256>>>();
    k_final<<<1,32>>>(out);
}

// round 9
// speedup vs baseline: 4.8112x; 1.0265x over previous
#include <cuda_runtime.h>
#include <cuda_bf16.h>
#include <stdint.h>
#include <math.h>

#define BB 32
#define TT 64
#define VV 8000
#define EE 256
#define HH 512
#define GG 2048
#define WW 3
#define NEGF (-1e30f)
#define NDROW 4096
#define ROWS_E 64
#define PDT 68
#define PDROWS (PDT*BB)      // 2176
#define NP 250               // vocab partial strips of 32
#define SR (4*NDROW)

typedef __nv_bfloat16 bf16;

// ----- scratch -----
__device__ float d_Xe[TT*ROWS_E*GG];
__device__ float d_Henc[2*(TT+1)*BB*HH];
__device__ float d_Pd[2*PDROWS*GG];
__device__ bf16  d_GB[NDROW*GG];            // decoder gates (bf16)
__device__ float d_Cdec[2*NDROW*HH];
__device__ int   d_tokE[TT*ROWS_E];
__device__ int   d_tokD[2*PDROWS];
__device__ float d_zc[3*NDROW];
__device__ float d_zt[4*NDROW];
__device__ float d_part[NP*SR*2];
__device__ float d_lse[4*NDROW];
__device__ float d_res[2*TT*WW*BB];
__device__ unsigned g_cnt;
__device__ unsigned g_gen;

// ----- bf16 mirrors -----
__device__ bf16 d_embB[VV*EE];
__device__ bf16 d_WeIB[GG*EE];
__device__ bf16 d_WfIB[GG*EE];
__device__ bf16 d_WbIB[GG*EE];
__device__ bf16 d_WfHB[GG*HH];
__device__ bf16 d_WbHB[GG*HH];
__device__ bf16 d_hWfB[VV*HH];
__device__ bf16 d_hWbB[VV*HH];
__device__ bf16 d_HencB[2*(TT+1)*BB*HH];
__device__ bf16 d_HdecB[5*NDROW*HH];

__device__ __forceinline__ float sigm(float x){ return 1.f/(1.f+__expf(-x)); }
__device__ __forceinline__ unsigned sptr(const void* p){
    return (unsigned)__cvta_generic_to_shared(p);
}
__device__ __forceinline__ void ldsm4(unsigned* r, unsigned a){
    asm volatile("ldmatrix.sync.aligned.m8n8.x4.shared.b16 {%0,%1,%2,%3}, [%4];\n"
        : "=r"(r[0]),"=r"(r[1]),"=r"(r[2]),"=r"(r[3]) : "r"(a));
}
__device__ __forceinline__ void mma16(float* c, const unsigned* a, const unsigned* b){
    asm volatile("mma.sync.aligned.m16n8k16.row.col.f32.bf16.bf16.f32 "
        "{%0,%1,%2,%3},{%4,%5,%6,%7},{%8,%9},{%0,%1,%2,%3};\n"
        : "+f"(c[0]),"+f"(c[1]),"+f"(c[2]),"+f"(c[3])
        : "r"(a[0]),"r"(a[1]),"r"(a[2]),"r"(a[3]),"r"(b[0]),"r"(b[1]));
}
__device__ __forceinline__ void cp16(unsigned dst, const void* src, int ssz){
    asm volatile("cp.async.cg.shared.global [%0], [%1], 16, %2;\n"
        :: "r"(dst), "l"(src), "r"(ssz));
}

// ----- fp32 -> bf16 conversion (2 merged kernels) -----
__global__ void k_convA(const float* __restrict__ emb, const float* __restrict__ eWih,
                        const float* __restrict__ fWih, const float* __restrict__ bWih){
    const long n0 = (long)VV*EE, n1 = n0 + (long)GG*EE, n2 = n1 + (long)GG*EE, n3 = n2 + (long)GG*EE;
    long i = ((long)blockIdx.x*blockDim.x + threadIdx.x)*4;
    if (i >= n3) return;
    const float* src; bf16* dst; long off;
    if (i < n0){ src=emb; dst=d_embB; off=i; }
    else if (i < n1){ src=eWih; dst=d_WeIB; off=i-n0; }
    else if (i < n2){ src=fWih; dst=d_WfIB; off=i-n1; }
    else { src=bWih; dst=d_WbIB; off=i-n2; }
    float4 v = *(const float4*)(src+off);
    *(__nv_bfloat162*)(dst+off)   = __floats2bfloat162_rn(v.x, v.y);
    *(__nv_bfloat162*)(dst+off+2) = __floats2bfloat162_rn(v.z, v.w);
}
__global__ void k_convB(const float* __restrict__ fWhh, const float* __restrict__ bWhh,
                        const float* __restrict__ fhW, const float* __restrict__ bhW){
    const long n0 = (long)GG*HH, n1 = n0 + (long)GG*HH, n2 = n1 + (long)VV*HH, n3 = n2 + (long)VV*HH;
    long i = ((long)blockIdx.x*blockDim.x + threadIdx.x)*4;
    if (i >= n3) return;
    const float* src; bf16* dst; long off;
    if (i < n0){ src=fWhh; dst=d_WfHB; off=i; }
    else if (i < n1){ src=bWhh; dst=d_WbHB; off=i-n0; }
    else if (i < n2){ src=fhW; dst=d_hWfB; off=i-n1; }
    else { src=bhW; dst=d_hWbB; off=i-n2; }
    float4 v = *(const float4*)(src+off);
    *(__nv_bfloat162*)(dst+off)   = __floats2bfloat162_rn(v.x, v.y);
    *(__nv_bfloat162*)(dst+off+2) = __floats2bfloat162_rn(v.z, v.w);
}

// ----- init -----
__global__ void k_init(const int* __restrict__ sent){
    int i = blockIdx.x*blockDim.x + threadIdx.x;
    if (i == 0){ g_cnt = 0u; g_gen = 0u; }
    if (i < 2*BB*HH){
        int dir = i/(BB*HH); int rem = i%(BB*HH);
        d_HencB[(dir*(TT+1))*BB*HH + rem] = __float2bfloat16(0.f);
    }
    if (i < TT*ROWS_E){
        int t = i/ROWS_E, r = i%ROWS_E, dir = r/BB, b = r%BB;
        int tok = (t==0) ? 0 : (dir ? sent[b*TT + (TT-t)] : sent[b*TT + (t-1)]);
        d_tokE[i] = tok;
    }
    if (i < 2*PDROWS){
        int dir = i/PDROWS; int rem = i%PDROWS; int t = rem/BB, b = rem%BB;
        int tok = (t < TT) ? (dir ? sent[b*TT + (TT-1-t)] : sent[b*TT + t]) : 0;
        d_tokD[i] = tok;
    }
}

// ===================== bf16 mma.sync GEMM, K-chunk 32, 4-stage cp.async =====================
#define BG_SMEM (8*5120*2)     // 81920 bytes
extern __shared__ bf16 dynsm[];

template<int MODE>
__global__ void __launch_bounds__(256) k_bgemm(
    const float* __restrict__ bias0, const float* __restrict__ bias1,
    int gsel, int mhalf, int s)
{
    constexpr int KD = (MODE==0)? EE : HH;
    constexpr int NC = KD/32;
    bf16* sA = dynsm;                 // [4][128*40]
    bf16* sB = dynsm + 4*5120;        // [4][128*40]
    const int tid = threadIdx.x;
    const int m0 = blockIdx.y*128, n0 = blockIdx.x*128;
    const int ss = (MODE==2)? (int)blockIdx.z : s;
    const int dir = (m0 >= mhalf)? 1 : 0;
    const bf16* Bm;
    if (MODE==0) Bm = gsel? (dir? d_WbIB : d_WfIB) : d_WeIB;
    else if (MODE==1) Bm = dir? d_WbHB : d_WfHB;
    else Bm = dir? d_hWbB : d_hWfB;
    const float* bias = dir? bias1 : bias0;

    const int lrow = tid>>1, lc = (tid&1)*16;
    const bf16* arow;
    if (MODE==0){
        const int* tok = gsel? d_tokD : d_tokE;
        arow = d_embB + (long)tok[m0+lrow]*KD;
    } else if (MODE==1){
        arow = d_HdecB + (long)ss*NDROW*HH + (long)(m0+lrow)*HH;
    } else {
        arow = d_HdecB + (long)(ss+1)*NDROW*HH + (long)(m0+lrow)*HH;
    }
    const int vrow = n0 + lrow;
    const bool bval = (MODE!=2) || (vrow < VV);
    const bf16* brow = Bm + (long)(bval? vrow : 0)*KD;
    const int bok = bval? 16 : 0;

    const unsigned smA = sptr(sA), smB = sptr(sB);
    const unsigned ldoff = (unsigned)(lrow*80 + (tid&1)*32);

    auto issue_chunk = [&](int kt, int st){
        int k0 = kt*32;
        unsigned adst = smA + (unsigned)st*10240u + ldoff;
        cp16(adst,      arow + k0 + lc,     16);
        cp16(adst+16u,  arow + k0 + lc + 8, 16);
        unsigned bdst = smB + (unsigned)st*10240u + ldoff;
        cp16(bdst,      brow + k0 + lc,     bok);
        cp16(bdst+16u,  brow + k0 + lc + 8, bok);
        asm volatile("cp.async.commit_group;" ::: "memory");
    };

    const int lane = tid&31, warp = tid>>5;
    const int wm = warp&1, wn = warp>>1;
    const int g = lane>>2, t4 = lane&3;
    const int rl = (lane&7) + ((lane>>3)&1)*8;
    const int ca = (lane>>4)*8;
    const int rb = (lane&7) + ((lane>>4)&1)*8;
    const int cb = ((lane>>3)&1)*8;

    float acc[4][4][4];
    #pragma unroll
    for (int i=0;i<4;i++)
        #pragma unroll
        for (int j=0;j<4;j++)
            #pragma unroll
            for (int e=0;e<4;e++) acc[i][j][e]=0.f;

    issue_chunk(0, 0);
    issue_chunk(1, 1);
    issue_chunk(2, 2);

    #pragma unroll 1
    for (int kt=0; kt<NC; kt++){
        asm volatile("cp.async.wait_group 2;" ::: "memory");
        __syncthreads();
        int nx = kt + 3;
        if (nx < NC) issue_chunk(nx, nx&3);
        else asm volatile("cp.async.commit_group;" ::: "memory");
        const bf16* Ab = sA + (kt&3)*5120;
        const bf16* Bb = sB + (kt&3)*5120;
        #pragma unroll
        for (int ks=0; ks<32; ks+=16){
            unsigned af[4][4], bfm[2][4];
            #pragma unroll
            for (int mf=0;mf<4;mf++)
                ldsm4(af[mf], sptr(Ab + (wm*64+mf*16+rl)*40 + ks + ca));
            #pragma unroll
            for (int p=0;p<2;p++)
                ldsm4(bfm[p], sptr(Bb + (wn*32+p*16+rb)*40 + ks + cb));
            #pragma unroll
            for (int mf=0;mf<4;mf++)
                #pragma unroll
                for (int nf=0;nf<4;nf++)
                    mma16(acc[mf][nf], af[mf], &bfm[nf>>1][(nf&1)*2]);
        }
    }

    if (MODE==0){
        float* Co = gsel? d_Pd : d_Xe;
        #pragma unroll
        for (int mf=0; mf<4; mf++)
            #pragma unroll
            for (int lohi=0; lohi<2; lohi++){
                int r = m0 + wm*64 + mf*16 + g + lohi*8;
                #pragma unroll
                for (int nf=0; nf<4; nf++){
                    int col = n0 + wn*32 + nf*8 + 2*t4;
                    float2 o;
                    o.x = acc[mf][nf][lohi*2+0] + bias[col];
                    o.y = acc[mf][nf][lohi*2+1] + bias[col+1];
                    *(float2*)&Co[(long)r*GG + col] = o;
                }
            }
    } else if (MODE==1){
        #pragma unroll
        for (int mf=0; mf<4; mf++)
            #pragma unroll
            for (int lohi=0; lohi<2; lohi++){
                int r = m0 + wm*64 + mf*16 + g + lohi*8;
                int rr = r - dir*2048;
                int m = rr>>5, b2 = rr&31;
                int tp = (ss==0)? TT : min(m+ss-1, TT-1);
                const float* xr = d_Pd + ((long)(dir*PDT+tp)*BB + b2)*GG;
                #pragma unroll
                for (int nf=0; nf<4; nf++){
                    int col = n0 + wn*32 + nf*8 + 2*t4;
                    float gx = acc[mf][nf][lohi*2+0] + xr[col];
                    float gy = acc[mf][nf][lohi*2+1] + xr[col+1];
                    *(__nv_bfloat162*)&d_GB[(long)r*GG + col] = __floats2bfloat162_rn(gx, gy);
                }
            }
    } else {
        int nb = (n0>>5) + wn;
        #pragma unroll
        for (int mf=0; mf<4; mf++)
            #pragma unroll
            for (int lohi=0; lohi<2; lohi++){
                int r = m0 + wm*64 + mf*16 + g + lohi*8;
                float z[8]; float mx = NEGF;
                #pragma unroll
                for (int nf=0; nf<4; nf++)
                    #pragma unroll
                    for (int e=0; e<2; e++){
                        int v = n0 + wn*32 + nf*8 + 2*t4 + e;
                        float zz = acc[mf][nf][lohi*2+e] + ((v<VV)? bias[v] : NEGF);
                        z[nf*2+e] = zz;
                        mx = fmaxf(mx, zz);
                    }
                mx = fmaxf(mx, __shfl_xor_sync(0xffffffffu, mx, 1));
                mx = fmaxf(mx, __shfl_xor_sync(0xffffffffu, mx, 2));
                float sm = 0.f;
                #pragma unroll
                for (int j=0;j<8;j++) sm += __expf(z[j]-mx);
                sm += __shfl_xor_sync(0xffffffffu, sm, 1);
                sm += __shfl_xor_sync(0xffffffffu, sm, 2);
                if (t4 == 0 && nb < NP){
                    int srow = ss*NDROW + r;
                    d_part[((long)nb*SR + srow)*2    ] = mx;
                    d_part[((long)nb*SR + srow)*2 + 1] = sm;
                }
            }
    }
}

// ===================== tensor-core persistent encoder (full-H cp.async stage) =====================
#define ESM_BYTES (64*520*2 + 64*520*2 + 64*66*4)
__global__ void __launch_bounds__(256) k_enc(const float* __restrict__ Whh){
    extern __shared__ char esm[];
    bf16* Ws  = (bf16*)esm;
    bf16* As  = Ws + 64*520;
    float* Gs = (float*)(As + 64*520);
    const int tid = threadIdx.x;
    const int h0 = blockIdx.x*16;

    {
        int c = tid>>2, t4w = tid&3;
        int gg = c&3, q = c>>2;
        const float* wr = Whh + (long)(gg*HH + h0 + q)*HH + t4w*128;
        bf16* dst = Ws + c*520 + t4w*128;
        #pragma unroll 4
        for (int j=0;j<128;j+=4){
            float4 v = *(const float4*)(wr+j);
            dst[j]   = __float2bfloat16_rn(v.x);
            dst[j+1] = __float2bfloat16_rn(v.y);
            dst[j+2] = __float2bfloat16_rn(v.z);
            dst[j+3] = __float2bfloat16_rn(v.w);
        }
    }
    __syncthreads();

    const int lane = tid&31, warp = tid>>5;
    const int wr4 = warp&3, wc = warp>>2;
    const int g = lane>>2, t4 = lane&3;
    const int rl = (lane&7) + ((lane>>3)&1)*8;
    const int ca = (lane>>4)*8;
    const int rb = (lane&7) + ((lane>>4)&1)*8;
    const int cb = ((lane>>3)&1)*8;
    const int srow = tid>>2, qd = tid&3;
    const int sdir = srow>>5, sb = srow&31;
    const int r = tid>>2, l4 = tid&3;
    const int dir = r>>5, b = r&31;

    const unsigned asbase = sptr(As) + (unsigned)((srow*520 + qd*128)*2);

    float cst[4] = {0.f,0.f,0.f,0.f};
    unsigned gen = 0;

    for (int t=0; t<TT; t++){
        {
            const bf16* src = d_HencB + ((long)(sdir*(TT+1)+t)*BB + sb)*HH + qd*128;
            #pragma unroll
            for (int i=0;i<16;i++) cp16(asbase + i*16u, src + i*8, 16);
            asm volatile("cp.async.commit_group;" ::: "memory");
            asm volatile("cp.async.wait_group 0;" ::: "memory");
        }
        __syncthreads();

        float acc[4][4];
        #pragma unroll
        for (int nf=0;nf<4;nf++)
            #pragma unroll
            for (int e=0;e<4;e++) acc[nf][e]=0.f;

        #pragma unroll 4
        for (int ks=0; ks<512; ks+=16){
            unsigned af[4], bfm[2][4];
            ldsm4(af, sptr(As + (16*wr4+rl)*520 + ks + ca));
            #pragma unroll
            for (int p=0;p<2;p++)
                ldsm4(bfm[p], sptr(Ws + (wc*32+p*16+rb)*520 + ks + cb));
            #pragma unroll
            for (int nf=0;nf<4;nf++)
                mma16(acc[nf], af, &bfm[nf>>1][(nf&1)*2]);
        }
        #pragma unroll
        for (int nf=0;nf<4;nf++){
            int col = wc*32 + nf*8 + 2*t4;
            Gs[(16*wr4+g)*66 + col]   = acc[nf][0];
            Gs[(16*wr4+g)*66 + col+1] = acc[nf][1];
            Gs[(16*wr4+g+8)*66 + col]   = acc[nf][2];
            Gs[(16*wr4+g+8)*66 + col+1] = acc[nf][3];
        }
        __syncthreads();
        {
            const float* xb = d_Xe + (long)(t*ROWS_E + r)*GG;
            #pragma unroll
            for (int j=0;j<4;j++){
                int q = l4 + 4*j; int h = h0 + q;
                float gi = Gs[r*66 + 4*q + 0] + xb[h];
                float gf = Gs[r*66 + 4*q + 1] + xb[HH+h];
                float g2 = Gs[r*66 + 4*q + 2] + xb[2*HH+h];
                float go = Gs[r*66 + 4*q + 3] + xb[3*HH+h];
                cst[j] = sigm(gf)*cst[j] + sigm(gi)*tanhf(g2);
                float hn = sigm(go)*tanhf(cst[j]);
                long oi = ((long)(dir*(TT+1)+(t+1))*BB + b)*HH + h;
                d_Henc[oi]  = hn;
                d_HencB[oi] = __float2bfloat16_rn(hn);
            }
        }
        __threadfence();
        __syncthreads();
        if (tid==0){
            unsigned a = atomicAdd(&g_cnt, 1u);
            if (a == gridDim.x-1){
                g_cnt = 0;
                __threadfence();
                atomicExch(&g_gen, gen+1u);
            } else {
                while (*((volatile unsigned*)&g_gen) != gen+1u) __nanosleep(32);
                __threadfence();
            }
        }
        __syncthreads();
        gen++;
    }
}

// ----- decoder init -----
__global__ void k_decinit(){
    int i = blockIdx.x*blockDim.x + threadIdx.x;
    int row = i>>9, h = i&511;
    int dir = row>>11, rr = row&2047, m = rr>>5, b = rr&31;
    float v = d_Henc[((long)(dir*(TT+1)+(m+1))*BB+b)*HH + h];
    d_Cdec[i] = v;
    d_HdecB[i] = __float2bfloat16_rn(v);
}

// ----- decoder cell (bf16 gates) -----
__global__ void k_cell(int s){
    int i = blockIdx.x*blockDim.x + threadIdx.x;
    int row = i>>9, h = i&511;
    const bf16* gr = d_GB + (long)row*GG;
    float gi = __bfloat162float(gr[h]);
    float gf = __bfloat162float(gr[HH+h]);
    float g2 = __bfloat162float(gr[2*HH+h]);
    float go = __bfloat162float(gr[3*HH+h]);
    float cp = d_Cdec[(s&1)*NDROW*HH + i];
    float c = sigm(gf)*cp + sigm(gi)*tanhf(g2);
    float hn = sigm(go)*tanhf(c);
    d_Cdec[((s+1)&1)*NDROW*HH + i] = c;
    d_HdecB[(long)(s+1)*NDROW*HH + i] = __float2bfloat16_rn(hn);
}

// ----- gathered picks (bf16 inputs, fp32 accumulate) -----
__global__ void k_picks(const float* __restrict__ fhb, const float* __restrict__ bhb){
    int w = (blockIdx.x*blockDim.x + threadIdx.x) >> 5;
    int lane = threadIdx.x & 31;
    if (w >= 6*NDROW) return;
    int kind = w / NDROW;
    int row  = w % NDROW;
    int dir = row>>11, rr = row&2047, m = rr>>5, b = rr&31;
    const bf16* hW = dir ? d_hWbB : d_hWfB;
    const float* hb = dir ? bhb : fhb;
    int s, y;
    if (kind < 3){ s = kind;   y = d_tokD[dir*PDROWS + min(m+s, TT-1)*BB + b]; }
    else         { s = kind-2; y = 0; }
    const bf16* h = d_HdecB + (long)(s+1)*NDROW*HH + (long)row*HH;
    const bf16* wv = hW + (long)y*HH;
    float sum = 0.f;
    #pragma unroll 4
    for (int k=lane*2; k<HH; k+=64){
        __nv_bfloat162 a = *(const __nv_bfloat162*)(h+k);
        __nv_bfloat162 x = *(const __nv_bfloat162*)(wv+k);
        sum += __bfloat162float(a.x)*__bfloat162float(x.x)
             + __bfloat162float(a.y)*__bfloat162float(x.y);
    }
    #pragma unroll
    for (int off=16; off; off>>=1) sum += __shfl_xor_sync(0xffffffffu, sum, off);
    if (!lane){
        if (kind < 3) d_zc[s*NDROW + row] = sum + hb[y];
        else          d_zt[s*NDROW + row] = sum + hb[0];
    }
}

// ----- combine LSE partials -----
__global__ void k_lse2(){
    int i = blockIdx.x*blockDim.x + threadIdx.x;
    if (i >= SR) return;
    float mx = NEGF, sm = 0.f;
    for (int nb=0; nb<NP; nb++){
        float2 p = *(float2*)&d_part[((long)nb*SR + i)*2];
        if (p.x > mx){ sm = sm*__expf(mx-p.x) + p.y; mx = p.x; }
        else sm += p.y*__expf(p.x-mx);
    }
    d_lse[i] = mx + logf(sm);
}

// ----- segment scores -----
__global__ void k_res(){
    int i = blockIdx.x*blockDim.x + threadIdx.x;
    if (i >= NDROW) return;
    int dir = i>>11, rr = i&2047, m = rr>>5, b = rr&31;
    float cum = 0.f;
    #pragma unroll
    for (int l=0; l<WW; l++){
        cum += d_zc[l*NDROW+i] - d_lse[l*NDROW+i];
        float tg = d_zt[(l+1)*NDROW+i] - d_lse[(l+1)*NDROW+i];
        d_res[((dir*TT+m)*WW+l)*BB + b] = cum + tg;
    }
}

// ----- final DP -----
__global__ void k_final(float* __restrict__ out){
    int b = threadIdx.x;
    float w0 = 0.f, w1 = NEGF, w2 = NEGF;
    for (int e=0; e<TT; e++){
        float p[3];
        #pragma unroll
        for (int l=0; l<3; l++){
            int st = e - l;
            p[l] = (st >= 0) ? (d_res[((0*TT+st)*WW+l)*BB + b]
                              + d_res[((1*TT+(TT-1-e))*WW+l)*BB + b]) : NEGF;
        }
        float x0 = w0+p[0], x1 = w1+p[1], x2 = w2+p[2];
        float m = fmaxf(x0, fmaxf(x1, x2));
        float tot = m + logf(__expf(x0-m) + __expf(x1-m) + __expf(x2-m));
        w2 = w1; w1 = w0; w0 = tot;
    }
    float v = w0;
    #pragma unroll
    for (int off=16; off; off>>=1) v += __shfl_xor_sync(0xffffffffu, v, off);
    if (b == 0) out[0] = -v/(float)BB;
}

extern "C" void kernel_launch(void* const* d_in, const int* in_sizes, int n_in,
                              void* d_out, int out_size){
    const int*   sent = (const int*)  d_in[0];
    const float* emb  = (const float*)d_in[1];
    const float* eWih = (const float*)d_in[2];
    const float* eWhh = (const float*)d_in[3];
    const float* eB   = (const float*)d_in[4];
    const float* fWih = (const float*)d_in[5];
    const float* fWhh = (const float*)d_in[6];
    const float* fB   = (const float*)d_in[7];
    const float* fhW  = (const float*)d_in[8];
    const float* fhb  = (const float*)d_in[9];
    const float* bWih = (const float*)d_in[10];
    const float* bWhh = (const float*)d_in[11];
    const float* bB   = (const float*)d_in[12];
    const float* bhW  = (const float*)d_in[13];
    const float* bhb  = (const float*)d_in[14];
    float* out = (float*)d_out;

    cudaFuncSetAttribute(k_enc, cudaFuncAttributeMaxDynamicSharedMemorySize, ESM_BYTES);
    cudaFuncSetAttribute(k_bgemm<0>, cudaFuncAttributeMaxDynamicSharedMemorySize, BG_SMEM);
    cudaFuncSetAttribute(k_bgemm<1>, cudaFuncAttributeMaxDynamicSharedMemorySize, BG_SMEM);
    cudaFuncSetAttribute(k_bgemm<2>, cudaFuncAttributeMaxDynamicSharedMemorySize, BG_SMEM);

    k_init<<<128,256>>>(sent);
    {
        long nA = (long)VV*EE + 3L*GG*EE;
        long nB = 2L*GG*HH + 2L*VV*HH;
        k_convA<<<(int)((nA/4+255)/256),256>>>(emb, eWih, fWih, bWih);
        k_convB<<<(int)((nB/4+255)/256),256>>>(fWhh, bWhh, fhW, bhW);
    }
    k_bgemm<0><<<dim3(16,32,1),256,BG_SMEM>>>(eB, eB, 0, 1<<30, 0);
    k_bgemm<0><<<dim3(16,34,1),256,BG_SMEM>>>(fB, bB, 1, PDROWS, 0);
    k_enc<<<32,256,ESM_BYTES>>>(eWhh);
    k_decinit<<<8192,256>>>();
    for (int s=0; s<4; s++){
        k_bgemm<1><<<dim3(16,32,1),256,BG_SMEM>>>(0, 0, 0, 2048, s);
        k_cell<<<4096,512>>>(s);
    }
    k_picks<<<3072,256>>>(fhb, bhb);
    k_bgemm<2><<<dim3(63,32,4),256,BG_SMEM>>>(fhb, bhb, 0, 2048, 0);
    k_lse2<<<64,256>>>();
    k_res<<<16,256>>>();
    k_final<<<1,32>>>(out);
}

// round 11
// speedup vs baseline: 5.2505x; 1.0913x over previous
#include <cuda_runtime.h>
#include <cuda_bf16.h>
#include <stdint.h>
#include <math.h>

#define BB 32
#define TT 64
#define VV 8000
#define EE 256
#define HH 512
#define GG 2048
#define WW 3
#define NEGF (-1e30f)
#define NDROW 4096
#define ROWS_E 64
#define PDT 68
#define PDROWS (PDT*BB)      // 2176
#define NP 250               // vocab partial strips of 32
#define SR (4*NDROW)

typedef __nv_bfloat16 bf16;

// ----- scratch -----
__device__ float d_Xe[TT*ROWS_E*GG];
__device__ float d_Henc[2*(TT+1)*BB*HH];
__device__ float d_Pd[2*PDROWS*GG];
__device__ bf16  d_GB[NDROW*GG];            // decoder gates (bf16)
__device__ float d_Cdec[2*NDROW*HH];
__device__ int   d_tokE[TT*ROWS_E];
__device__ int   d_tokD[2*PDROWS];
__device__ float d_zc[3*NDROW];
__device__ float d_zt[4*NDROW];
__device__ float d_part[NP*SR*2];
__device__ float d_lse[4*NDROW];
__device__ float d_res[2*TT*WW*BB];
__device__ unsigned g_cnt;
__device__ unsigned g_gen;

// ----- bf16 mirrors -----
__device__ bf16 d_embB[VV*EE];
__device__ bf16 d_WeIB[GG*EE];
__device__ bf16 d_WfIB[GG*EE];
__device__ bf16 d_WbIB[GG*EE];
__device__ bf16 d_WfHB[GG*HH];
__device__ bf16 d_WbHB[GG*HH];
__device__ bf16 d_hWfB[VV*HH];
__device__ bf16 d_hWbB[VV*HH];
__device__ bf16 d_HencB[2*(TT+1)*BB*HH];
__device__ bf16 d_HdecB[5*NDROW*HH];

__device__ __forceinline__ float sigm(float x){ return 1.f/(1.f+__expf(-x)); }
__device__ __forceinline__ unsigned sptr(const void* p){
    return (unsigned)__cvta_generic_to_shared(p);
}
__device__ __forceinline__ void ldsm4(unsigned* r, unsigned a){
    asm volatile("ldmatrix.sync.aligned.m8n8.x4.shared.b16 {%0,%1,%2,%3}, [%4];\n"
        : "=r"(r[0]),"=r"(r[1]),"=r"(r[2]),"=r"(r[3]) : "r"(a));
}
__device__ __forceinline__ void mma16(float* c, const unsigned* a, const unsigned* b){
    asm volatile("mma.sync.aligned.m16n8k16.row.col.f32.bf16.bf16.f32 "
        "{%0,%1,%2,%3},{%4,%5,%6,%7},{%8,%9},{%0,%1,%2,%3};\n"
        : "+f"(c[0]),"+f"(c[1]),"+f"(c[2]),"+f"(c[3])
        : "r"(a[0]),"r"(a[1]),"r"(a[2]),"r"(a[3]),"r"(b[0]),"r"(b[1]));
}
__device__ __forceinline__ void cp16(unsigned dst, const void* src, int ssz){
    asm volatile("cp.async.cg.shared.global [%0], [%1], 16, %2;\n"
        :: "r"(dst), "l"(src), "r"(ssz));
}

// ----- fp32 -> bf16 conversion (2 merged kernels) -----
__global__ void k_convA(const float* __restrict__ emb, const float* __restrict__ eWih,
                        const float* __restrict__ fWih, const float* __restrict__ bWih){
    const long n0 = (long)VV*EE, n1 = n0 + (long)GG*EE, n2 = n1 + (long)GG*EE, n3 = n2 + (long)GG*EE;
    long i = ((long)blockIdx.x*blockDim.x + threadIdx.x)*4;
    if (i >= n3) return;
    const float* src; bf16* dst; long off;
    if (i < n0){ src=emb; dst=d_embB; off=i; }
    else if (i < n1){ src=eWih; dst=d_WeIB; off=i-n0; }
    else if (i < n2){ src=fWih; dst=d_WfIB; off=i-n1; }
    else { src=bWih; dst=d_WbIB; off=i-n2; }
    float4 v = *(const float4*)(src+off);
    *(__nv_bfloat162*)(dst+off)   = __floats2bfloat162_rn(v.x, v.y);
    *(__nv_bfloat162*)(dst+off+2) = __floats2bfloat162_rn(v.z, v.w);
}
__global__ void k_convB(const float* __restrict__ fWhh, const float* __restrict__ bWhh,
                        const float* __restrict__ fhW, const float* __restrict__ bhW){
    const long n0 = (long)GG*HH, n1 = n0 + (long)GG*HH, n2 = n1 + (long)VV*HH, n3 = n2 + (long)VV*HH;
    long i = ((long)blockIdx.x*blockDim.x + threadIdx.x)*4;
    if (i >= n3) return;
    const float* src; bf16* dst; long off;
    if (i < n0){ src=fWhh; dst=d_WfHB; off=i; }
    else if (i < n1){ src=bWhh; dst=d_WbHB; off=i-n0; }
    else if (i < n2){ src=fhW; dst=d_hWfB; off=i-n1; }
    else { src=bhW; dst=d_hWbB; off=i-n2; }
    float4 v = *(const float4*)(src+off);
    *(__nv_bfloat162*)(dst+off)   = __floats2bfloat162_rn(v.x, v.y);
    *(__nv_bfloat162*)(dst+off+2) = __floats2bfloat162_rn(v.z, v.w);
}

// ----- init -----
__global__ void k_init(const int* __restrict__ sent){
    int i = blockIdx.x*blockDim.x + threadIdx.x;
    if (i == 0){ g_cnt = 0u; g_gen = 0u; }
    if (i < 2*BB*HH){
        int dir = i/(BB*HH); int rem = i%(BB*HH);
        d_HencB[(dir*(TT+1))*BB*HH + rem] = __float2bfloat16(0.f);
    }
    if (i < TT*ROWS_E){
        int t = i/ROWS_E, r = i%ROWS_E, dir = r/BB, b = r%BB;
        int tok = (t==0) ? 0 : (dir ? sent[b*TT + (TT-t)] : sent[b*TT + (t-1)]);
        d_tokE[i] = tok;
    }
    if (i < 2*PDROWS){
        int dir = i/PDROWS; int rem = i%PDROWS; int t = rem/BB, b = rem%BB;
        int tok = (t < TT) ? (dir ? sent[b*TT + (TT-1-t)] : sent[b*TT + t]) : 0;
        d_tokD[i] = tok;
    }
}

// ===================== bf16 mma.sync GEMM: 512 threads, 16 warps, warp-tile 32x32 =====================
// 128x128 CTA tile, K-chunk 32, 3-stage cp.async. smem: [3][A 128x40 | B 128x40]
#define BG_SMEM (6*5120*2)     // 61440 bytes
extern __shared__ bf16 dynsm[];

template<int MODE>
__global__ void __launch_bounds__(512,2) k_bgemm(
    const float* __restrict__ bias0, const float* __restrict__ bias1,
    int gsel, int mhalf, int s)
{
    constexpr int KD = (MODE==0)? EE : HH;
    constexpr int NC = KD/32;
    bf16* sA = dynsm;                 // [3][128*40]
    bf16* sB = dynsm + 3*5120;        // [3][128*40]
    const int tid = threadIdx.x;
    const int m0 = blockIdx.y*128, n0 = blockIdx.x*128;
    const int ss = (MODE==2)? (int)blockIdx.z : s;
    const int dir = (m0 >= mhalf)? 1 : 0;
    const bf16* Bm;
    if (MODE==0) Bm = gsel? (dir? d_WbIB : d_WfIB) : d_WeIB;
    else if (MODE==1) Bm = dir? d_WbHB : d_WfHB;
    else Bm = dir? d_hWbB : d_hWfB;
    const float* bias = dir? bias1 : bias0;

    const int lrow = tid>>2, lc = (tid&3)*8;     // 4 threads/row, 8 bf16 each
    const bf16* arow;
    if (MODE==0){
        const int* tok = gsel? d_tokD : d_tokE;
        arow = d_embB + (long)tok[m0+lrow]*KD;
    } else if (MODE==1){
        arow = d_HdecB + (long)ss*NDROW*HH + (long)(m0+lrow)*HH;
    } else {
        arow = d_HdecB + (long)(ss+1)*NDROW*HH + (long)(m0+lrow)*HH;
    }
    const int vrow = n0 + lrow;
    const bool bval = (MODE!=2) || (vrow < VV);
    const bf16* brow = Bm + (long)(bval? vrow : 0)*KD;
    const int bok = bval? 16 : 0;

    const unsigned smA = sptr(sA), smB = sptr(sB);
    const unsigned ldoff = (unsigned)((lrow*40 + lc)*2);

    auto issue_chunk = [&](int kt, int st){
        int k0 = kt*32;
        cp16(smA + (unsigned)st*10240u + ldoff, arow + k0 + lc, 16);
        cp16(smB + (unsigned)st*10240u + ldoff, brow + k0 + lc, bok);
        asm volatile("cp.async.commit_group;" ::: "memory");
    };

    const int lane = tid&31, warp = tid>>5;      // 16 warps
    const int wm = warp&3, wn = warp>>2;         // 4x4 warp grid, 32x32 tiles
    const int g = lane>>2, t4 = lane&3;
    const int rl = (lane&7) + ((lane>>3)&1)*8;
    const int ca = (lane>>4)*8;
    const int rb = (lane&7) + ((lane>>4)&1)*8;
    const int cb = ((lane>>3)&1)*8;

    float acc[2][4][4];
    #pragma unroll
    for (int i=0;i<2;i++)
        #pragma unroll
        for (int j=0;j<4;j++)
            #pragma unroll
            for (int e=0;e<4;e++) acc[i][j][e]=0.f;

    issue_chunk(0, 0);
    issue_chunk(1, 1);

    #pragma unroll 1
    for (int kt=0; kt<NC; kt++){
        asm volatile("cp.async.wait_group 1;" ::: "memory");
        __syncthreads();
        int nx = kt + 2;
        if (nx < NC) issue_chunk(nx, nx%3);
        else asm volatile("cp.async.commit_group;" ::: "memory");
        const bf16* Ab = sA + (kt%3)*5120;
        const bf16* Bb = sB + (kt%3)*5120;
        #pragma unroll
        for (int ks=0; ks<32; ks+=16){
            unsigned af[2][4], bfm[2][4];
            #pragma unroll
            for (int mf=0;mf<2;mf++)
                ldsm4(af[mf], sptr(Ab + (wm*32+mf*16+rl)*40 + ks + ca));
            #pragma unroll
            for (int p=0;p<2;p++)
                ldsm4(bfm[p], sptr(Bb + (wn*32+p*16+rb)*40 + ks + cb));
            #pragma unroll
            for (int mf=0;mf<2;mf++)
                #pragma unroll
                for (int nf=0;nf<4;nf++)
                    mma16(acc[mf][nf], af[mf], &bfm[nf>>1][(nf&1)*2]);
        }
    }

    if (MODE==0){
        float* Co = gsel? d_Pd : d_Xe;
        #pragma unroll
        for (int mf=0; mf<2; mf++)
            #pragma unroll
            for (int lohi=0; lohi<2; lohi++){
                int r = m0 + wm*32 + mf*16 + g + lohi*8;
                #pragma unroll
                for (int nf=0; nf<4; nf++){
                    int col = n0 + wn*32 + nf*8 + 2*t4;
                    float2 o;
                    o.x = acc[mf][nf][lohi*2+0] + bias[col];
                    o.y = acc[mf][nf][lohi*2+1] + bias[col+1];
                    *(float2*)&Co[(long)r*GG + col] = o;
                }
            }
    } else if (MODE==1){
        #pragma unroll
        for (int mf=0; mf<2; mf++)
            #pragma unroll
            for (int lohi=0; lohi<2; lohi++){
                int r = m0 + wm*32 + mf*16 + g + lohi*8;
                int rr = r - dir*2048;
                int m = rr>>5, b2 = rr&31;
                int tp = (ss==0)? TT : min(m+ss-1, TT-1);
                const float* xr = d_Pd + ((long)(dir*PDT+tp)*BB + b2)*GG;
                #pragma unroll
                for (int nf=0; nf<4; nf++){
                    int col = n0 + wn*32 + nf*8 + 2*t4;
                    float gx = acc[mf][nf][lohi*2+0] + xr[col];
                    float gy = acc[mf][nf][lohi*2+1] + xr[col+1];
                    *(__nv_bfloat162*)&d_GB[(long)r*GG + col] = __floats2bfloat162_rn(gx, gy);
                }
            }
    } else {
        int nb = (n0>>5) + wn;
        #pragma unroll
        for (int mf=0; mf<2; mf++)
            #pragma unroll
            for (int lohi=0; lohi<2; lohi++){
                int r = m0 + wm*32 + mf*16 + g + lohi*8;
                float z[8]; float mx = NEGF;
                #pragma unroll
                for (int nf=0; nf<4; nf++)
                    #pragma unroll
                    for (int e=0; e<2; e++){
                        int v = n0 + wn*32 + nf*8 + 2*t4 + e;
                        float zz = acc[mf][nf][lohi*2+e] + ((v<VV)? bias[v] : NEGF);
                        z[nf*2+e] = zz;
                        mx = fmaxf(mx, zz);
                    }
                mx = fmaxf(mx, __shfl_xor_sync(0xffffffffu, mx, 1));
                mx = fmaxf(mx, __shfl_xor_sync(0xffffffffu, mx, 2));
                float sm = 0.f;
                #pragma unroll
                for (int j=0;j<8;j++) sm += __expf(z[j]-mx);
                sm += __shfl_xor_sync(0xffffffffu, sm, 1);
                sm += __shfl_xor_sync(0xffffffffu, sm, 2);
                if (t4 == 0 && nb < NP){
                    int srow = ss*NDROW + r;
                    d_part[((long)nb*SR + srow)*2    ] = mx;
                    d_part[((long)nb*SR + srow)*2 + 1] = sm;
                }
            }
    }
}

// ===================== tensor-core persistent encoder (full-H cp.async stage) =====================
#define ESM_BYTES (64*520*2 + 64*520*2 + 64*66*4)
__global__ void __launch_bounds__(256) k_enc(const float* __restrict__ Whh){
    extern __shared__ char esm[];
    bf16* Ws  = (bf16*)esm;
    bf16* As  = Ws + 64*520;
    float* Gs = (float*)(As + 64*520);
    const int tid = threadIdx.x;
    const int h0 = blockIdx.x*16;

    {
        int c = tid>>2, t4w = tid&3;
        int gg = c&3, q = c>>2;
        const float* wr = Whh + (long)(gg*HH + h0 + q)*HH + t4w*128;
        bf16* dst = Ws + c*520 + t4w*128;
        #pragma unroll 4
        for (int j=0;j<128;j+=4){
            float4 v = *(const float4*)(wr+j);
            dst[j]   = __float2bfloat16_rn(v.x);
            dst[j+1] = __float2bfloat16_rn(v.y);
            dst[j+2] = __float2bfloat16_rn(v.z);
            dst[j+3] = __float2bfloat16_rn(v.w);
        }
    }
    __syncthreads();

    const int lane = tid&31, warp = tid>>5;
    const int wr4 = warp&3, wc = warp>>2;
    const int g = lane>>2, t4 = lane&3;
    const int rl = (lane&7) + ((lane>>3)&1)*8;
    const int ca = (lane>>4)*8;
    const int rb = (lane&7) + ((lane>>4)&1)*8;
    const int cb = ((lane>>3)&1)*8;
    const int srow = tid>>2, qd = tid&3;
    const int sdir = srow>>5, sb = srow&31;
    const int r = tid>>2, l4 = tid&3;
    const int dir = r>>5, b = r&31;

    const unsigned asbase = sptr(As) + (unsigned)((srow*520 + qd*128)*2);

    float cst[4] = {0.f,0.f,0.f,0.f};
    unsigned gen = 0;

    for (int t=0; t<TT; t++){
        {
            const bf16* src = d_HencB + ((long)(sdir*(TT+1)+t)*BB + sb)*HH + qd*128;
            #pragma unroll
            for (int i=0;i<16;i++) cp16(asbase + i*16u, src + i*8, 16);
            asm volatile("cp.async.commit_group;" ::: "memory");
            asm volatile("cp.async.wait_group 0;" ::: "memory");
        }
        __syncthreads();

        float acc[4][4];
        #pragma unroll
        for (int nf=0;nf<4;nf++)
            #pragma unroll
            for (int e=0;e<4;e++) acc[nf][e]=0.f;

        #pragma unroll 4
        for (int ks=0; ks<512; ks+=16){
            unsigned af[4], bfm[2][4];
            ldsm4(af, sptr(As + (16*wr4+rl)*520 + ks + ca));
            #pragma unroll
            for (int p=0;p<2;p++)
                ldsm4(bfm[p], sptr(Ws + (wc*32+p*16+rb)*520 + ks + cb));
            #pragma unroll
            for (int nf=0;nf<4;nf++)
                mma16(acc[nf], af, &bfm[nf>>1][(nf&1)*2]);
        }
        #pragma unroll
        for (int nf=0;nf<4;nf++){
            int col = wc*32 + nf*8 + 2*t4;
            Gs[(16*wr4+g)*66 + col]   = acc[nf][0];
            Gs[(16*wr4+g)*66 + col+1] = acc[nf][1];
            Gs[(16*wr4+g+8)*66 + col]   = acc[nf][2];
            Gs[(16*wr4+g+8)*66 + col+1] = acc[nf][3];
        }
        __syncthreads();
        {
            const float* xb = d_Xe + (long)(t*ROWS_E + r)*GG;
            #pragma unroll
            for (int j=0;j<4;j++){
                int q = l4 + 4*j; int h = h0 + q;
                float gi = Gs[r*66 + 4*q + 0] + xb[h];
                float gf = Gs[r*66 + 4*q + 1] + xb[HH+h];
                float g2 = Gs[r*66 + 4*q + 2] + xb[2*HH+h];
                float go = Gs[r*66 + 4*q + 3] + xb[3*HH+h];
                cst[j] = sigm(gf)*cst[j] + sigm(gi)*tanhf(g2);
                float hn = sigm(go)*tanhf(cst[j]);
                long oi = ((long)(dir*(TT+1)+(t+1))*BB + b)*HH + h;
                d_Henc[oi]  = hn;
                d_HencB[oi] = __float2bfloat16_rn(hn);
            }
        }
        __threadfence();
        __syncthreads();
        if (tid==0){
            unsigned a = atomicAdd(&g_cnt, 1u);
            if (a == gridDim.x-1){
                g_cnt = 0;
                __threadfence();
                atomicExch(&g_gen, gen+1u);
            } else {
                while (*((volatile unsigned*)&g_gen) != gen+1u) __nanosleep(32);
                __threadfence();
            }
        }
        __syncthreads();
        gen++;
    }
}

// ----- decoder init -----
__global__ void k_decinit(){
    int i = blockIdx.x*blockDim.x + threadIdx.x;
    int row = i>>9, h = i&511;
    int dir = row>>11, rr = row&2047, m = rr>>5, b = rr&31;
    float v = d_Henc[((long)(dir*(TT+1)+(m+1))*BB+b)*HH + h];
    d_Cdec[i] = v;
    d_HdecB[i] = __float2bfloat16_rn(v);
}

// ----- decoder cell (bf16 gates) -----
__global__ void k_cell(int s){
    int i = blockIdx.x*blockDim.x + threadIdx.x;
    int row = i>>9, h = i&511;
    const bf16* gr = d_GB + (long)row*GG;
    float gi = __bfloat162float(gr[h]);
    float gf = __bfloat162float(gr[HH+h]);
    float g2 = __bfloat162float(gr[2*HH+h]);
    float go = __bfloat162float(gr[3*HH+h]);
    float cp = d_Cdec[(s&1)*NDROW*HH + i];
    float c = sigm(gf)*cp + sigm(gi)*tanhf(g2);
    float hn = sigm(go)*tanhf(c);
    d_Cdec[((s+1)&1)*NDROW*HH + i] = c;
    d_HdecB[(long)(s+1)*NDROW*HH + i] = __float2bfloat16_rn(hn);
}

// ----- gathered picks (bf16 inputs, fp32 accumulate) -----
__global__ void k_picks(const float* __restrict__ fhb, const float* __restrict__ bhb){
    int w = (blockIdx.x*blockDim.x + threadIdx.x) >> 5;
    int lane = threadIdx.x & 31;
    if (w >= 6*NDROW) return;
    int kind = w / NDROW;
    int row  = w % NDROW;
    int dir = row>>11, rr = row&2047, m = rr>>5, b = rr&31;
    const bf16* hW = dir ? d_hWbB : d_hWfB;
    const float* hb = dir ? bhb : fhb;
    int s, y;
    if (kind < 3){ s = kind;   y = d_tokD[dir*PDROWS + min(m+s, TT-1)*BB + b]; }
    else         { s = kind-2; y = 0; }
    const bf16* h = d_HdecB + (long)(s+1)*NDROW*HH + (long)row*HH;
    const bf16* wv = hW + (long)y*HH;
    float sum = 0.f;
    #pragma unroll 4
    for (int k=lane*2; k<HH; k+=64){
        __nv_bfloat162 a = *(const __nv_bfloat162*)(h+k);
        __nv_bfloat162 x = *(const __nv_bfloat162*)(wv+k);
        sum += __bfloat162float(a.x)*__bfloat162float(x.x)
             + __bfloat162float(a.y)*__bfloat162float(x.y);
    }
    #pragma unroll
    for (int off=16; off; off>>=1) sum += __shfl_xor_sync(0xffffffffu, sum, off);
    if (!lane){
        if (kind < 3) d_zc[s*NDROW + row] = sum + hb[y];
        else          d_zt[s*NDROW + row] = sum + hb[0];
    }
}

// ----- combine LSE partials -----
__global__ void k_lse2(){
    int i = blockIdx.x*blockDim.x + threadIdx.x;
    if (i >= SR) return;
    float mx = NEGF, sm = 0.f;
    for (int nb=0; nb<NP; nb++){
        float2 p = *(float2*)&d_part[((long)nb*SR + i)*2];
        if (p.x > mx){ sm = sm*__expf(mx-p.x) + p.y; mx = p.x; }
        else sm += p.y*__expf(p.x-mx);
    }
    d_lse[i] = mx + logf(sm);
}

// ----- segment scores -----
__global__ void k_res(){
    int i = blockIdx.x*blockDim.x + threadIdx.x;
    if (i >= NDROW) return;
    int dir = i>>11, rr = i&2047, m = rr>>5, b = rr&31;
    float cum = 0.f;
    #pragma unroll
    for (int l=0; l<WW; l++){
        cum += d_zc[l*NDROW+i] - d_lse[l*NDROW+i];
        float tg = d_zt[(l+1)*NDROW+i] - d_lse[(l+1)*NDROW+i];
        d_res[((dir*TT+m)*WW+l)*BB + b] = cum + tg;
    }
}

// ----- final DP -----
__global__ void k_final(float* __restrict__ out){
    int b = threadIdx.x;
    float w0 = 0.f, w1 = NEGF, w2 = NEGF;
    for (int e=0; e<TT; e++){
        float p[3];
        #pragma unroll
        for (int l=0; l<3; l++){
            int st = e - l;
            p[l] = (st >= 0) ? (d_res[((0*TT+st)*WW+l)*BB + b]
                              + d_res[((1*TT+(TT-1-e))*WW+l)*BB + b]) : NEGF;
        }
        float x0 = w0+p[0], x1 = w1+p[1], x2 = w2+p[2];
        float m = fmaxf(x0, fmaxf(x1, x2));
        float tot = m + logf(__expf(x0-m) + __expf(x1-m) + __expf(x2-m));
        w2 = w1; w1 = w0; w0 = tot;
    }
    float v = w0;
    #pragma unroll
    for (int off=16; off; off>>=1) v += __shfl_xor_sync(0xffffffffu, v, off);
    if (b == 0) out[0] = -v/(float)BB;
}

extern "C" void kernel_launch(void* const* d_in, const int* in_sizes, int n_in,
                              void* d_out, int out_size){
    const int*   sent = (const int*)  d_in[0];
    const float* emb  = (const float*)d_in[1];
    const float* eWih = (const float*)d_in[2];
    const float* eWhh = (const float*)d_in[3];
    const float* eB   = (const float*)d_in[4];
    const float* fWih = (const float*)d_in[5];
    const float* fWhh = (const float*)d_in[6];
    const float* fB   = (const float*)d_in[7];
    const float* fhW  = (const float*)d_in[8];
    const float* fhb  = (const float*)d_in[9];
    const float* bWih = (const float*)d_in[10];
    const float* bWhh = (const float*)d_in[11];
    const float* bB   = (const float*)d_in[12];
    const float* bhW  = (const float*)d_in[13];
    const float* bhb  = (const float*)d_in[14];
    float* out = (float*)d_out;

    cudaFuncSetAttribute(k_enc, cudaFuncAttributeMaxDynamicSharedMemorySize, ESM_BYTES);
    cudaFuncSetAttribute(k_bgemm<0>, cudaFuncAttributeMaxDynamicSharedMemorySize, BG_SMEM);
    cudaFuncSetAttribute(k_bgemm<1>, cudaFuncAttributeMaxDynamicSharedMemorySize, BG_SMEM);
    cudaFuncSetAttribute(k_bgemm<2>, cudaFuncAttributeMaxDynamicSharedMemorySize, BG_SMEM);

    k_init<<<128,256>>>(sent);
    {
        long nA = (long)VV*EE + 3L*GG*EE;
        long nB = 2L*GG*HH + 2L*VV*HH;
        k_convA<<<(int)((nA/4+255)/256),256>>>(emb, eWih, fWih, bWih);
        k_convB<<<(int)((nB/4+255)/256),256>>>(fWhh, bWhh, fhW, bhW);
    }
    k_bgemm<0><<<dim3(16,32,1),512,BG_SMEM>>>(eB, eB, 0, 1<<30, 0);
    k_bgemm<0><<<dim3(16,34,1),512,BG_SMEM>>>(fB, bB, 1, PDROWS, 0);
    k_enc<<<32,256,ESM_BYTES>>>(eWhh);
    k_decinit<<<8192,256>>>();
    for (int s=0; s<4; s++){
        k_bgemm<1><<<dim3(16,32,1),512,BG_SMEM>>>(0, 0, 0, 2048, s);
        k_cell<<<4096,512>>>(s);
    }
    k_picks<<<3072,256>>>(fhb, bhb);
    k_bgemm<2><<<dim3(63,32,4),512,BG_SMEM>>>(fhb, bhb, 0, 2048, 0);
    k_lse2<<<64,256>>>();
    k_res<<<16,256>>>();
    k_final<<<1,32>>>(out);
}